// round 15
// baseline (speedup 1.0000x reference)
#include <cuda_runtime.h>
#include <cuda_bf16.h>
#include <math.h>
#include <stdint.h>

#define NPTS 200000
#define MPTS 100000

// ---------------- scratch (device globals: allocation-free rule) ----------
__device__ float g_fx[NPTS * 32];
__device__ float g_gx[NPTS * 32];
__device__ float g_gw1[NPTS * 8];
__device__ float g_pemax[MPTS * 32];
__device__ float g_pw1[(size_t)MPTS * 16 * 8];
__device__ float g_w[(size_t)MPTS * 16 * 16];
__device__ __nv_bfloat16 g_aggh[(size_t)MPTS * 512];
__device__ __nv_bfloat16 g_aggl[(size_t)MPTS * 512];
__device__ __nv_bfloat16 g_sfh[(size_t)MPTS * 64];
__device__ __nv_bfloat16 g_sfl[(size_t)MPTS * 64];
__device__ __nv_bfloat16 g_bh[64 * 512];
__device__ __nv_bfloat16 g_bl[64 * 512];
__device__ __nv_bfloat16 g_b2h[128 * 128];
__device__ __nv_bfloat16 g_b2l[128 * 128];

__device__ __forceinline__ float relu_f(float x) { return x > 0.f ? x : 0.f; }
__device__ __forceinline__ float lrelu_f(float x) { return x > 0.f ? x : 0.1f * x; }

__device__ __forceinline__ uint32_t smem_u32(const void* p) {
    uint32_t a;
    asm("{ .reg .u64 t; cvta.to.shared.u64 t, %1; cvt.u32.u64 %0, t; }" : "=r"(a) : "l"(p));
    return a;
}
__device__ __forceinline__ void ldsm4(uint32_t* r, uint32_t a) {
    asm volatile("ldmatrix.sync.aligned.m8n8.x4.shared.b16 {%0,%1,%2,%3}, [%4];"
                 : "=r"(r[0]), "=r"(r[1]), "=r"(r[2]), "=r"(r[3]) : "r"(a));
}
__device__ __forceinline__ void mma16816(float* d, const uint32_t* a, const uint32_t* b) {
    asm volatile(
        "mma.sync.aligned.m16n8k16.row.col.f32.bf16.bf16.f32 "
        "{%0,%1,%2,%3}, {%4,%5,%6,%7}, {%8,%9}, {%0,%1,%2,%3};"
        : "+f"(d[0]), "+f"(d[1]), "+f"(d[2]), "+f"(d[3])
        : "r"(a[0]), "r"(a[1]), "r"(a[2]), "r"(a[3]), "r"(b[0]), "r"(b[1]));
}
__device__ __forceinline__ void cp16(uint32_t dst, const void* src) {
    asm volatile("cp.async.cg.shared.global [%0], [%1], 16;" :: "r"(dst), "l"(src));
}
#define CP_COMMIT() asm volatile("cp.async.commit_group;" ::: "memory")
#define CP_WAIT1() asm volatile("cp.async.wait_group 1;" ::: "memory")
#define CP_WAIT0() asm volatile("cp.async.wait_group 0;" ::: "memory")

__device__ __forceinline__ uint32_t pack_hi2(float x, float y, uint32_t& lo) {
    __nv_bfloat16 hx = __float2bfloat16(x);
    __nv_bfloat16 hy = __float2bfloat16(y);
    __nv_bfloat16 lx = __float2bfloat16(x - __bfloat162float(hx));
    __nv_bfloat16 ly = __float2bfloat16(y - __bfloat162float(hy));
    lo = ((uint32_t)__bfloat16_as_ushort(ly) << 16) | __bfloat16_as_ushort(lx);
    return ((uint32_t)__bfloat16_as_ushort(hy) << 16) | __bfloat16_as_ushort(hx);
}

// ======================= fused front kernel ================================
// block types striped: per group of 11 -> 8 x k5, 2 x k6, 1 x k1; k0 appended.
#define NGRP 1563
#define NB_STRIPE (NGRP * 11)       // 17193
#define NB_FRONT (NB_STRIPE + 128)  // 17321

struct SmemK1 {
    float w1[2048];    // [k][c] 64x32
    float wgu[1024];   // 32x32
    float wg1k[256];   // 32x8
    float u[128 * 68]; // f tile; fx reused at stride 36
};
struct SmemK6 {
    float wpet[384], w1h[256], wn1t[96], wn2t[64], wn3t[128];
    float bpe[32], bn1[8], bn2[8], bn3[16];
    float tmp[256 * 36];
};
union SmemFront {
    SmemK1 k1;
    SmemK6 k6;
};

// ---------- k1 body: dense transform + gw1 ----------
__device__ void k1_body(SmemK1* s, int blk,
                        const float* __restrict__ df,
                        const float* __restrict__ w1, const float* __restrict__ b1,
                        const float* __restrict__ wgu, const float* __restrict__ bgu,
                        const float* __restrict__ wg1) {
    int t = threadIdx.x;
    int p0 = blk * 128;
    for (int i = t; i < 2048; i += 256) s->w1[i] = w1[i];
    for (int i = t; i < 1024; i += 256) s->wgu[i] = wgu[i];
    if (t < 256) s->wg1k[t] = wg1[t];
#pragma unroll
    for (int q = 0; q < 8; q++) {
        int id = t + q * 256;
        int pp = id >> 4, kk = (id & 15) * 4;
        int gm = p0 + pp; if (gm >= NPTS) gm = NPTS - 1;
        *(float4*)&s->u[pp * 68 + kk] = *(const float4*)(df + (size_t)gm * 64 + kk);
    }
    __syncthreads();

    int pg = t >> 3, cg = t & 7;
    int c4 = cg * 4;
    float4 bb = *(const float4*)(b1 + c4);
    float acc[4][4];
#pragma unroll
    for (int i = 0; i < 4; i++) { acc[i][0] = bb.x; acc[i][1] = bb.y; acc[i][2] = bb.z; acc[i][3] = bb.w; }
#pragma unroll
    for (int kb = 0; kb < 64; kb += 4) {
        float4 a[4];
#pragma unroll
        for (int i = 0; i < 4; i++) a[i] = *(const float4*)&s->u[(pg * 4 + i) * 68 + kb];
#pragma unroll
        for (int q = 0; q < 4; q++) {
            float4 w = *(const float4*)&s->w1[(kb + q) * 32 + c4];
#pragma unroll
            for (int i = 0; i < 4; i++) {
                float av = q == 0 ? a[i].x : q == 1 ? a[i].y : q == 2 ? a[i].z : a[i].w;
                acc[i][0] = fmaf(av, w.x, acc[i][0]); acc[i][1] = fmaf(av, w.y, acc[i][1]);
                acc[i][2] = fmaf(av, w.z, acc[i][2]); acc[i][3] = fmaf(av, w.w, acc[i][3]);
            }
        }
    }
    float4 fxv[4];
#pragma unroll
    for (int i = 0; i < 4; i++)
        fxv[i] = make_float4(lrelu_f(acc[i][0]), lrelu_f(acc[i][1]), lrelu_f(acc[i][2]), lrelu_f(acc[i][3]));
    __syncthreads();   // all reads of u (f layout) done
#pragma unroll
    for (int i = 0; i < 4; i++) {
        int gm = p0 + pg * 4 + i;
        *(float4*)&s->u[(pg * 4 + i) * 36 + c4] = fxv[i];
        if (gm < NPTS) *(float4*)(g_fx + (size_t)gm * 32 + c4) = fxv[i];
    }
    __syncthreads();

    float4 bg = *(const float4*)(bgu + c4);
    float gac[4][4];
#pragma unroll
    for (int i = 0; i < 4; i++) { gac[i][0] = bg.x; gac[i][1] = bg.y; gac[i][2] = bg.z; gac[i][3] = bg.w; }
#pragma unroll
    for (int kb = 0; kb < 32; kb += 4) {
        float4 a[4];
#pragma unroll
        for (int i = 0; i < 4; i++) a[i] = *(const float4*)&s->u[(pg * 4 + i) * 36 + kb];
#pragma unroll
        for (int q = 0; q < 4; q++) {
            float4 w = *(const float4*)&s->wgu[(kb + q) * 32 + c4];
#pragma unroll
            for (int i = 0; i < 4; i++) {
                float av = q == 0 ? a[i].x : q == 1 ? a[i].y : q == 2 ? a[i].z : a[i].w;
                gac[i][0] = fmaf(av, w.x, gac[i][0]); gac[i][1] = fmaf(av, w.y, gac[i][1]);
                gac[i][2] = fmaf(av, w.z, gac[i][2]); gac[i][3] = fmaf(av, w.w, gac[i][3]);
            }
        }
    }
    __syncthreads();   // all reads of u (fx=feats_x) done
#pragma unroll
    for (int i = 0; i < 4; i++) {
        int gm = p0 + pg * 4 + i;
        *(float4*)&s->u[(pg * 4 + i) * 36 + c4] =
            make_float4(gac[i][0], gac[i][1], gac[i][2], gac[i][3]);
        if (gm < NPTS)
            *(float4*)(g_gx + (size_t)gm * 32 + c4) =
                make_float4(gac[i][0], gac[i][1], gac[i][2], gac[i][3]);
    }
    __syncthreads();

    {
        int p2 = t >> 1, h4 = (t & 1) * 4;
        float o4[4] = {0.f, 0.f, 0.f, 0.f};
#pragma unroll
        for (int c = 0; c < 32; c++) {
            float g = s->u[p2 * 36 + c];
            float4 w = *(const float4*)&s->wg1k[c * 8 + h4];
            o4[0] = fmaf(g, w.x, o4[0]); o4[1] = fmaf(g, w.y, o4[1]);
            o4[2] = fmaf(g, w.z, o4[2]); o4[3] = fmaf(g, w.w, o4[3]);
        }
        int gm = p0 + p2;
        if (gm < NPTS)
            *(float4*)(g_gw1 + (size_t)gm * 8 + h4) = make_float4(o4[0], o4[1], o4[2], o4[3]);
    }
}

// ---------- k6 body: PE/WeightNet + pe channel-max ----------
__device__ void k6_body(SmemK6* s, int blk,
                        const float* __restrict__ vi_f,
                        const float* __restrict__ wpe, const float* __restrict__ bpe,
                        const float* __restrict__ wg1,
                        const float* __restrict__ wn1, const float* __restrict__ bn1,
                        const float* __restrict__ wn2, const float* __restrict__ bn2,
                        const float* __restrict__ wn3, const float* __restrict__ bn3) {
    int t = threadIdx.x;
    for (int i = t; i < 384; i += 256) { int c = i / 12, ii = i % 12; s->wpet[i] = wpe[ii * 32 + c]; }
    if (t < 256) s->w1h[t] = wg1[256 + t];
    if (t < 96) { int o = t / 12, ii = t % 12; s->wn1t[t] = wn1[ii * 8 + o]; }
    if (t < 64) s->wn2t[t] = wn2[(t & 7) * 8 + (t >> 3)];
    if (t < 128) { int o = t >> 3, ii = t & 7; s->wn3t[t] = wn3[ii * 16 + o]; }
    if (t < 32) s->bpe[t] = bpe[t];
    if (t < 8) { s->bn1[t] = bn1[t]; s->bn2[t] = bn2[t]; }
    if (t < 16) s->bn3[t] = bn3[t];
    __syncthreads();

    size_t r0 = (size_t)blk * 512 + t * 2;
    float va[12], vb[12];
    {
        const float4* p = (const float4*)(vi_f + r0 * 12);
        float4 x0 = p[0], x1 = p[1], x2 = p[2], x3 = p[3], x4 = p[4], x5 = p[5];
        va[0] = x0.x; va[1] = x0.y; va[2] = x0.z; va[3] = x0.w;
        va[4] = x1.x; va[5] = x1.y; va[6] = x1.z; va[7] = x1.w;
        va[8] = x2.x; va[9] = x2.y; va[10] = x2.z; va[11] = x2.w;
        vb[0] = x3.x; vb[1] = x3.y; vb[2] = x3.z; vb[3] = x3.w;
        vb[4] = x4.x; vb[5] = x4.y; vb[6] = x4.z; vb[7] = x4.w;
        vb[8] = x5.x; vb[9] = x5.y; vb[10] = x5.z; vb[11] = x5.w;
    }

    float pwa[8], pwb[8];
#pragma unroll
    for (int h = 0; h < 8; h++) { pwa[h] = 0.f; pwb[h] = 0.f; }
#pragma unroll
    for (int c = 0; c < 32; c++) {
        const float4* wr = (const float4*)&s->wpet[c * 12];
        float4 w0 = wr[0], w1v = wr[1], w2 = wr[2];
        float bias = s->bpe[c];
        float a = bias, b = bias;
        a = fmaf(va[0], w0.x, a);  b = fmaf(vb[0], w0.x, b);
        a = fmaf(va[1], w0.y, a);  b = fmaf(vb[1], w0.y, b);
        a = fmaf(va[2], w0.z, a);  b = fmaf(vb[2], w0.z, b);
        a = fmaf(va[3], w0.w, a);  b = fmaf(vb[3], w0.w, b);
        a = fmaf(va[4], w1v.x, a); b = fmaf(vb[4], w1v.x, b);
        a = fmaf(va[5], w1v.y, a); b = fmaf(vb[5], w1v.y, b);
        a = fmaf(va[6], w1v.z, a); b = fmaf(vb[6], w1v.z, b);
        a = fmaf(va[7], w1v.w, a); b = fmaf(vb[7], w1v.w, b);
        a = fmaf(va[8], w2.x, a);  b = fmaf(vb[8], w2.x, b);
        a = fmaf(va[9], w2.y, a);  b = fmaf(vb[9], w2.y, b);
        a = fmaf(va[10], w2.z, a); b = fmaf(vb[10], w2.z, b);
        a = fmaf(va[11], w2.w, a); b = fmaf(vb[11], w2.w, b);
        float ra = relu_f(a), rb = relu_f(b);
        s->tmp[t * 36 + c] = fmaxf(ra, rb);
        const float4* wh = (const float4*)&s->w1h[c * 8];
        float4 ha = wh[0], hb = wh[1];
        pwa[0] = fmaf(ra, ha.x, pwa[0]); pwa[1] = fmaf(ra, ha.y, pwa[1]);
        pwa[2] = fmaf(ra, ha.z, pwa[2]); pwa[3] = fmaf(ra, ha.w, pwa[3]);
        pwa[4] = fmaf(ra, hb.x, pwa[4]); pwa[5] = fmaf(ra, hb.y, pwa[5]);
        pwa[6] = fmaf(ra, hb.z, pwa[6]); pwa[7] = fmaf(ra, hb.w, pwa[7]);
        pwb[0] = fmaf(rb, ha.x, pwb[0]); pwb[1] = fmaf(rb, ha.y, pwb[1]);
        pwb[2] = fmaf(rb, ha.z, pwb[2]); pwb[3] = fmaf(rb, ha.w, pwb[3]);
        pwb[4] = fmaf(rb, hb.x, pwb[4]); pwb[5] = fmaf(rb, hb.y, pwb[5]);
        pwb[6] = fmaf(rb, hb.z, pwb[6]); pwb[7] = fmaf(rb, hb.w, pwb[7]);
    }
    *(float4*)(g_pw1 + r0 * 8) = make_float4(pwa[0], pwa[1], pwa[2], pwa[3]);
    *(float4*)(g_pw1 + r0 * 8 + 4) = make_float4(pwa[4], pwa[5], pwa[6], pwa[7]);
    *(float4*)(g_pw1 + (r0 + 1) * 8) = make_float4(pwb[0], pwb[1], pwb[2], pwb[3]);
    *(float4*)(g_pw1 + (r0 + 1) * 8 + 4) = make_float4(pwb[4], pwb[5], pwb[6], pwb[7]);

    float h1a[8], h1b[8];
#pragma unroll
    for (int o = 0; o < 8; o++) {
        const float4* wr = (const float4*)&s->wn1t[o * 12];
        float4 w0 = wr[0], w1v = wr[1], w2 = wr[2];
        float bias = s->bn1[o];
        float a = bias, b = bias;
        a = fmaf(va[0], w0.x, a);  b = fmaf(vb[0], w0.x, b);
        a = fmaf(va[1], w0.y, a);  b = fmaf(vb[1], w0.y, b);
        a = fmaf(va[2], w0.z, a);  b = fmaf(vb[2], w0.z, b);
        a = fmaf(va[3], w0.w, a);  b = fmaf(vb[3], w0.w, b);
        a = fmaf(va[4], w1v.x, a); b = fmaf(vb[4], w1v.x, b);
        a = fmaf(va[5], w1v.y, a); b = fmaf(vb[5], w1v.y, b);
        a = fmaf(va[6], w1v.z, a); b = fmaf(vb[6], w1v.z, b);
        a = fmaf(va[7], w1v.w, a); b = fmaf(vb[7], w1v.w, b);
        a = fmaf(va[8], w2.x, a);  b = fmaf(vb[8], w2.x, b);
        a = fmaf(va[9], w2.y, a);  b = fmaf(vb[9], w2.y, b);
        a = fmaf(va[10], w2.z, a); b = fmaf(vb[10], w2.z, b);
        a = fmaf(va[11], w2.w, a); b = fmaf(vb[11], w2.w, b);
        h1a[o] = relu_f(a); h1b[o] = relu_f(b);
    }
    float h2a[8], h2b[8];
#pragma unroll
    for (int o = 0; o < 8; o++) {
        const float4* wr = (const float4*)&s->wn2t[o * 8];
        float4 wx = wr[0], wy = wr[1];
        float bias = s->bn2[o];
        float a = bias, b = bias;
        a = fmaf(h1a[0], wx.x, a); b = fmaf(h1b[0], wx.x, b);
        a = fmaf(h1a[1], wx.y, a); b = fmaf(h1b[1], wx.y, b);
        a = fmaf(h1a[2], wx.z, a); b = fmaf(h1b[2], wx.z, b);
        a = fmaf(h1a[3], wx.w, a); b = fmaf(h1b[3], wx.w, b);
        a = fmaf(h1a[4], wy.x, a); b = fmaf(h1b[4], wy.x, b);
        a = fmaf(h1a[5], wy.y, a); b = fmaf(h1b[5], wy.y, b);
        a = fmaf(h1a[6], wy.z, a); b = fmaf(h1b[6], wy.z, b);
        a = fmaf(h1a[7], wy.w, a); b = fmaf(h1b[7], wy.w, b);
        h2a[o] = relu_f(a); h2b[o] = relu_f(b);
    }
    float pa[4], pb[4];
#pragma unroll
    for (int o = 0; o < 16; o++) {
        const float4* wr = (const float4*)&s->wn3t[o * 8];
        float4 wx = wr[0], wy = wr[1];
        float bias = s->bn3[o];
        float a = bias, b = bias;
        a = fmaf(h2a[0], wx.x, a); b = fmaf(h2b[0], wx.x, b);
        a = fmaf(h2a[1], wx.y, a); b = fmaf(h2b[1], wx.y, b);
        a = fmaf(h2a[2], wx.z, a); b = fmaf(h2b[2], wx.z, b);
        a = fmaf(h2a[3], wx.w, a); b = fmaf(h2b[3], wx.w, b);
        a = fmaf(h2a[4], wy.x, a); b = fmaf(h2b[4], wy.x, b);
        a = fmaf(h2a[5], wy.y, a); b = fmaf(h2b[5], wy.y, b);
        a = fmaf(h2a[6], wy.z, a); b = fmaf(h2b[6], wy.z, b);
        a = fmaf(h2a[7], wy.w, a); b = fmaf(h2b[7], wy.w, b);
        pa[o & 3] = relu_f(a); pb[o & 3] = relu_f(b);
        if ((o & 3) == 3) {
            *(float4*)(g_w + r0 * 16 + (o - 3)) = make_float4(pa[0], pa[1], pa[2], pa[3]);
            *(float4*)(g_w + (r0 + 1) * 16 + (o - 3)) = make_float4(pb[0], pb[1], pb[2], pb[3]);
        }
    }

    __syncthreads();
    int pt = t >> 3, ch0 = (t & 7) * 4;
    int base = pt * 8;
    float4 vm = *(const float4*)&s->tmp[base * 36 + ch0];
#pragma unroll
    for (int k = 1; k < 8; k++) {
        float4 v = *(const float4*)&s->tmp[(base + k) * 36 + ch0];
        vm.x = fmaxf(vm.x, v.x); vm.y = fmaxf(vm.y, v.y);
        vm.z = fmaxf(vm.z, v.z); vm.w = fmaxf(vm.w, v.w);
    }
    *(float4*)(g_pemax + (size_t)(blk * 32 + pt) * 32 + ch0) = vm;
}

// ---------- k5 body: shortcut maxpool ----------
__device__ void k5_body(int blk, const float* __restrict__ df,
                        const int* __restrict__ nei) {
    const unsigned FULL = 0xffffffffu;
    int t = threadIdx.x;
    int wid = t >> 5, lane = t & 31;
    int m = blk * 8 + wid;
    int j = lane >> 1;
    int idx = __ldg(&nei[m * 16 + j]);
    float m0v = -3.0e38f, m1v = -3.0e38f;
#pragma unroll
    for (int jj = 0; jj < 16; jj++) {
        int ix = __shfl_sync(FULL, idx, jj * 2);
        m0v = fmaxf(m0v, __ldg(&df[(size_t)ix * 64 + lane]));
        m1v = fmaxf(m1v, __ldg(&df[(size_t)ix * 64 + 32 + lane]));
    }
    __nv_bfloat16 h0 = __float2bfloat16(m0v);
    __nv_bfloat16 h1b = __float2bfloat16(m1v);
    g_sfh[(size_t)m * 64 + lane] = h0;
    g_sfl[(size_t)m * 64 + lane] = __float2bfloat16(m0v - __bfloat162float(h0));
    g_sfh[(size_t)m * 64 + 32 + lane] = h1b;
    g_sfl[(size_t)m * 64 + 32 + lane] = __float2bfloat16(m1v - __bfloat162float(h1b));
}

// ---------- k0 body: weight conversions ----------
__device__ void k0_body(int blk,
                        const float* __restrict__ wlin, const float* __restrict__ wu2,
                        const float* __restrict__ wsc) {
    int i = blk * 256 + threadIdx.x;
    if (i < 512 * 64) {
        int n = i >> 9, k = i & 511;
        float v = __ldg(&wlin[k * 64 + n]);
        __nv_bfloat16 h = __float2bfloat16(v);
        g_bh[i] = h;
        g_bl[i] = __float2bfloat16(v - __bfloat162float(h));
    }
    if (i < 128 * 128) {
        int n = i >> 7, k = i & 127;
        float v = (k < 64) ? __ldg(&wu2[k * 128 + n]) : __ldg(&wsc[(k - 64) * 128 + n]);
        __nv_bfloat16 h = __float2bfloat16(v);
        g_b2h[i] = h;
        g_b2l[i] = __float2bfloat16(v - __bfloat162float(h));
    }
}

__global__ void __launch_bounds__(256) kfront(
    const float* __restrict__ df, const float* __restrict__ vi_f,
    const int* __restrict__ nei,
    const float* __restrict__ w1, const float* __restrict__ b1,
    const float* __restrict__ wgu, const float* __restrict__ bgu,
    const float* __restrict__ wpe, const float* __restrict__ bpe,
    const float* __restrict__ wg1,
    const float* __restrict__ wn1, const float* __restrict__ bn1,
    const float* __restrict__ wn2, const float* __restrict__ bn2,
    const float* __restrict__ wn3, const float* __restrict__ bn3,
    const float* __restrict__ wlin, const float* __restrict__ wu2,
    const float* __restrict__ wsc) {
    __shared__ SmemFront smem;
    int b = blockIdx.x;
    if (b < NB_STRIPE) {
        int g = b / 11, r = b % 11;
        if (r < 8) {
            int b5 = g * 8 + r;
            if (b5 < MPTS / 8) k5_body(b5, df, nei);
        } else if (r < 10) {
            int b6 = g * 2 + (r - 8);
            if (b6 < (MPTS * 16) / 512)
                k6_body(&smem.k6, b6, vi_f, wpe, bpe, wg1,
                        wn1, bn1, wn2, bn2, wn3, bn3);
        } else {
            k1_body(&smem.k1, g, df, w1, b1, wgu, bgu, wg1);
        }
    } else {
        k0_body(b - NB_STRIPE, wlin, wu2, wsc);
    }
}

// ======================= K2: gather + attention + agg ======================
__global__ void __launch_bounds__(256, 2) k2_point(
    const int* __restrict__ nei,
    const float* __restrict__ wg1, const float* __restrict__ bg1,
    const float* __restrict__ wg2, const float* __restrict__ bg2) {
    __shared__ __align__(16) float s_wg1[64 * 8];
    __shared__ __align__(16) float s_wg2t[8 * 8];
    __shared__ float s_bg1[8], s_bg2[8];
    __shared__ __align__(16) float s_gf[8][16][36];
    __shared__ __align__(16) float s_nf[8][16][36];
    __shared__ __align__(16) float s_w[8][16][20];
    int t = threadIdx.x;
    for (int i = t; i < 512; i += 256) s_wg1[i] = wg1[i];
    if (t < 64) s_wg2t[t] = wg2[(t & 7) * 8 + (t >> 3)];
    if (t < 8) { s_bg1[t] = bg1[t]; s_bg2[t] = bg2[t]; }
    __syncthreads();

    const unsigned FULL = 0xffffffffu;
    int wid = t >> 5, lane = t & 31;
    int j = lane >> 1, half = lane & 1;
    int m = blockIdx.x * 8 + wid;
    int idx = __ldg(&nei[m * 16 + j]);
    size_t row = (size_t)m * 16 + j;

    {
        const char* gsrc = (const char*)(g_gx + (size_t)idx * 32 + half * 16);
        uint32_t gdst = smem_u32(&s_gf[wid][j][half * 16]);
        cp16(gdst, gsrc); cp16(gdst + 16, gsrc + 16);
        cp16(gdst + 32, gsrc + 32); cp16(gdst + 48, gsrc + 48);
        const char* fsrc = (const char*)(g_fx + (size_t)idx * 32 + half * 16);
        uint32_t fdst = smem_u32(&s_nf[wid][j][half * 16]);
        cp16(fdst, fsrc); cp16(fdst + 16, fsrc + 16);
        cp16(fdst + 32, fsrc + 32); cp16(fdst + 48, fsrc + 48);
        const char* wsrc = (const char*)(g_w + row * 16 + half * 8);
        uint32_t wdst = smem_u32(&s_w[wid][j][half * 8]);
        cp16(wdst, wsrc); cp16(wdst + 16, wsrc + 16);
        CP_COMMIT();
    }
    float part[8];
    {
        const float* psrc = half ? (g_pw1 + row * 8) : (g_gw1 + (size_t)idx * 8);
        float4 a0 = __ldg((const float4*)psrc);
        float4 a1 = __ldg((const float4*)(psrc + 4));
        part[0] = a0.x; part[1] = a0.y; part[2] = a0.z; part[3] = a0.w;
        part[4] = a1.x; part[5] = a1.y; part[6] = a1.z; part[7] = a1.w;
    }
    float mx1 = __ldg(&g_pemax[(size_t)m * 32 + lane]);

    CP_WAIT0();
    __syncwarp();

    float mx0 = -3.0e38f;
    int cl = lane;
#pragma unroll
    for (int jj = 0; jj < 16; jj++)
        mx0 = fmaxf(mx0, s_gf[wid][jj][cl]);
    float mw[8];
    {
        const float4* wr0 = (const float4*)&s_wg1[cl * 8];
        const float4* wr1 = (const float4*)&s_wg1[(cl + 32) * 8];
        float4 a0 = wr0[0], a1 = wr0[1], b0 = wr1[0], b1v = wr1[1];
        mw[0] = fmaf(mx0, a0.x, mx1 * b0.x); mw[1] = fmaf(mx0, a0.y, mx1 * b0.y);
        mw[2] = fmaf(mx0, a0.z, mx1 * b0.z); mw[3] = fmaf(mx0, a0.w, mx1 * b0.w);
        mw[4] = fmaf(mx0, a1.x, mx1 * b1v.x); mw[5] = fmaf(mx0, a1.y, mx1 * b1v.y);
        mw[6] = fmaf(mx0, a1.z, mx1 * b1v.z); mw[7] = fmaf(mx0, a1.w, mx1 * b1v.w);
    }
#pragma unroll
    for (int s = 16; s >= 1; s >>= 1) {
#pragma unroll
        for (int h = 0; h < 8; h++) mw[h] += __shfl_xor_sync(FULL, mw[h], s);
    }
#pragma unroll
    for (int h = 0; h < 8; h++) part[h] += __shfl_xor_sync(FULL, part[h], 1);

    float s1v[8];
#pragma unroll
    for (int h = 0; h < 8; h++) s1v[h] = relu_f(part[h] - mw[h] + s_bg1[h]);
    float sc4[4];
#pragma unroll
    for (int hq = 0; hq < 4; hq++) {
        int h2 = half * 4 + hq;
        float a = s_bg2[h2];
        const float4* wr = (const float4*)&s_wg2t[h2 * 8];
        float4 wa = wr[0], wb = wr[1];
        a = fmaf(s1v[0], wa.x, a); a = fmaf(s1v[1], wa.y, a);
        a = fmaf(s1v[2], wa.z, a); a = fmaf(s1v[3], wa.w, a);
        a = fmaf(s1v[4], wb.x, a); a = fmaf(s1v[5], wb.y, a);
        a = fmaf(s1v[6], wb.z, a); a = fmaf(s1v[7], wb.w, a);
        sc4[hq] = 1.f / (1.f + __expf(-a));
    }

#pragma unroll
    for (int q = 0; q < 4; q++) {
        int c0 = half * 16 + 4 * q;
        float4 v = *(const float4*)&s_nf[wid][j][c0];
        float s = sc4[q];
        *(float4*)&s_nf[wid][j][c0] = make_float4(v.x * s, v.y * s, v.z * s, v.w * s);
    }
    __syncwarp();

    float acc[16];
#pragma unroll
    for (int w = 0; w < 16; w++) acc[w] = 0.f;
    int c = lane;
#pragma unroll
    for (int jj = 0; jj < 16; jj++) {
        float a = s_nf[wid][jj][c];
        const float4* wp = (const float4*)&s_w[wid][jj][0];
        float4 w0 = wp[0], w1v = wp[1], w2 = wp[2], w3 = wp[3];
        acc[0] = fmaf(a, w0.x, acc[0]);  acc[1] = fmaf(a, w0.y, acc[1]);
        acc[2] = fmaf(a, w0.z, acc[2]);  acc[3] = fmaf(a, w0.w, acc[3]);
        acc[4] = fmaf(a, w1v.x, acc[4]); acc[5] = fmaf(a, w1v.y, acc[5]);
        acc[6] = fmaf(a, w1v.z, acc[6]); acc[7] = fmaf(a, w1v.w, acc[7]);
        acc[8] = fmaf(a, w2.x, acc[8]);  acc[9] = fmaf(a, w2.y, acc[9]);
        acc[10] = fmaf(a, w2.z, acc[10]); acc[11] = fmaf(a, w2.w, acc[11]);
        acc[12] = fmaf(a, w3.x, acc[12]); acc[13] = fmaf(a, w3.y, acc[13]);
        acc[14] = fmaf(a, w3.z, acc[14]); acc[15] = fmaf(a, w3.w, acc[15]);
    }
    __align__(16) __nv_bfloat16 hb[16];
    __align__(16) __nv_bfloat16 lb[16];
#pragma unroll
    for (int w = 0; w < 16; w++) {
        float v = acc[w];
        __nv_bfloat16 h = __float2bfloat16(v);
        hb[w] = h;
        lb[w] = __float2bfloat16(v - __bfloat162float(h));
    }
    size_t bo = (size_t)m * 512 + c * 16;
    ((uint4*)(g_aggh + bo))[0] = ((uint4*)hb)[0];
    ((uint4*)(g_aggh + bo))[1] = ((uint4*)hb)[1];
    ((uint4*)(g_aggl + bo))[0] = ((uint4*)lb)[0];
    ((uint4*)(g_aggl + bo))[1] = ((uint4*)lb)[1];
}

// ======================= K34: fused GEMM1 + GEMM2 + epilogue ===============
#define K3_A_HI 0u
#define K3_A_LO 36864u
#define K3_B_HI 73728u
#define K3_B_LO 92160u
#define K4_A_HI 36864u
#define K4_A_LO 55296u
#define K4_B_HI 73728u
#define K4_B_LO 92160u
#define K34_SMEM 110592

__device__ __forceinline__ void k3_load(uint32_t sb, char* dsm, int t, int m0,
                                        int kt, int st) {
    uint32_t aofs = (uint32_t)st * 18432u;
    uint32_t bofs = (uint32_t)st * 9216u;
#pragma unroll
    for (int q = 0; q < 4; q++) {
        int id = t + q * 256;
        int row = id >> 3, seg = id & 7;
        int gm = m0 + row; if (gm >= MPTS) gm = MPTS - 1;
        size_t go = (size_t)gm * 512 + kt * 64 + seg * 8;
        uint32_t so_ = (uint32_t)(row * 144 + seg * 16);
        cp16(sb + K3_A_HI + aofs + so_, g_aggh + go);
        cp16(sb + K3_A_LO + aofs + so_, g_aggl + go);
    }
#pragma unroll
    for (int q = 0; q < 2; q++) {
        int id = t + q * 256;
        int n = id >> 3, seg = id & 7;
        size_t go = (size_t)n * 512 + kt * 64 + seg * 8;
        uint32_t so_ = (uint32_t)(n * 144 + seg * 16);
        cp16(sb + K3_B_HI + bofs + so_, g_bh + go);
        cp16(sb + K3_B_LO + bofs + so_, g_bl + go);
    }
}

__global__ void __launch_bounds__(256, 2) k34_out(
    const float* __restrict__ blin,
    const float* __restrict__ bu2, const float* __restrict__ bsc,
    float* __restrict__ out) {
    extern __shared__ __align__(16) char dsm[];
    uint32_t sb = smem_u32(dsm);
    int t = threadIdx.x;
    int wid = t >> 5, lane = t & 31;
    int m0 = blockIdx.x * 128;
    int wm = wid * 16;
    int qq = lane >> 3, rr = lane & 7;

    // ---------------- Phase 1: GEMM1 ----------------
    {
        float acc[8][4];
#pragma unroll
        for (int nt = 0; nt < 8; nt++)
#pragma unroll
            for (int q = 0; q < 4; q++) acc[nt][q] = 0.f;

        k3_load(sb, dsm, t, m0, 0, 0);
        CP_COMMIT();

#pragma unroll 1
        for (int kt = 0; kt < 8; kt++) {
            int st = kt & 1;
            if (kt < 7) {
                k3_load(sb, dsm, t, m0, kt + 1, st ^ 1);
                CP_COMMIT();
                CP_WAIT1();
            } else {
                CP_WAIT0();
            }
            __syncthreads();

            uint32_t aofs = (uint32_t)st * 18432u;
            uint32_t bofs = (uint32_t)st * 9216u;
#pragma unroll
            for (int ks = 0; ks < 4; ks++) {
                int k0 = ks * 16;
                uint32_t ah[4], al[4];
                {
                    int row = wm + rr + (qq & 1) * 8;
                    int col = k0 + (qq >> 1) * 8;
                    uint32_t ad = sb + K3_A_HI + aofs + (uint32_t)(row * 144 + col * 2);
                    ldsm4(ah, ad);
                    ldsm4(al, ad + (K3_A_LO - K3_A_HI));
                }
#pragma unroll
                for (int p = 0; p < 4; p++) {
                    uint32_t bh4[4], bl4[4];
                    int noff = 16 * p + rr + (qq >> 1) * 8;
                    int col = k0 + (qq & 1) * 8;
                    uint32_t bd = sb + K3_B_HI + bofs + (uint32_t)(noff * 144 + col * 2);
                    ldsm4(bh4, bd);
                    ldsm4(bl4, bd + (K3_B_LO - K3_B_HI));
                    mma16816(acc[2 * p], ah, bh4);
                    mma16816(acc[2 * p + 1], ah, bh4 + 2);
                    mma16816(acc[2 * p], al, bh4);
                    mma16816(acc[2 * p + 1], al, bh4 + 2);
                    mma16816(acc[2 * p], ah, bl4);
                    mma16816(acc[2 * p + 1], ah, bl4 + 2);
                }
            }
            __syncthreads();
        }

        {
            int rrow = lane >> 2, cp = (lane & 3) * 2;
            float* so = (float*)dsm;
#pragma unroll
            for (int nt = 0; nt < 8; nt++) {
                int c0 = nt * 8 + cp;
                float b0v = __ldg(&blin[c0]), b1v = __ldg(&blin[c0 + 1]);
                so[(wm + rrow) * 65 + c0]         = relu_f(acc[nt][0] + b0v);
                so[(wm + rrow) * 65 + c0 + 1]     = relu_f(acc[nt][1] + b1v);
                so[(wm + rrow + 8) * 65 + c0]     = relu_f(acc[nt][2] + b0v);
                so[(wm + rrow + 8) * 65 + c0 + 1] = relu_f(acc[nt][3] + b1v);
            }
        }
        __syncthreads();
    }

    // ---------------- Phase 2: GEMM2 + final epilogue ----------------
    float acc2[16][4];
#pragma unroll
    for (int nt = 0; nt < 16; nt++)
#pragma unroll
        for (int q = 0; q < 4; q++) acc2[nt][q] = 0.f;

#pragma unroll 1
    for (int kt = 0; kt < 2; kt++) {
        if (kt == 0) {
            const float* so = (const float*)dsm;
#pragma unroll
            for (int q = 0; q < 4; q++) {
                int id = t + q * 256;
                int row = id >> 3, seg = id & 7;
                uint32_t dA = sb + (uint32_t)(row * 144 + seg * 16);
                uint32_t hi0, hi1, hi2, hi3, lo0, lo1, lo2, lo3;
                const float* src = so + row * 65 + seg * 8;
                hi0 = pack_hi2(src[0], src[1], lo0);
                hi1 = pack_hi2(src[2], src[3], lo1);
                hi2 = pack_hi2(src[4], src[5], lo2);
                hi3 = pack_hi2(src[6], src[7], lo3);
                asm volatile("st.shared.v4.b32 [%0], {%1,%2,%3,%4};"
                             :: "r"(dA + K4_A_HI), "r"(hi0), "r"(hi1), "r"(hi2), "r"(hi3) : "memory");
                asm volatile("st.shared.v4.b32 [%0], {%1,%2,%3,%4};"
                             :: "r"(dA + K4_A_LO), "r"(lo0), "r"(lo1), "r"(lo2), "r"(lo3) : "memory");
            }
        } else {
#pragma unroll
            for (int q = 0; q < 4; q++) {
                int id = t + q * 256;
                int row = id >> 3, seg = id & 7;
                int gm = m0 + row; if (gm >= MPTS) gm = MPTS - 1;
                size_t go = (size_t)gm * 64 + seg * 8;
                uint32_t so_ = (uint32_t)(row * 144 + seg * 16);
                *(uint4*)(dsm + K4_A_HI + so_) = *(const uint4*)(g_sfh + go);
                *(uint4*)(dsm + K4_A_LO + so_) = *(const uint4*)(g_sfl + go);
            }
        }
#pragma unroll
        for (int q = 0; q < 4; q++) {
            int id = t + q * 256;
            int n = id >> 3, seg = id & 7;
            size_t go = (size_t)n * 128 + kt * 64 + seg * 8;
            uint32_t so_ = (uint32_t)(n * 144 + seg * 16);
            *(uint4*)(dsm + K4_B_HI + so_) = *(const uint4*)(g_b2h + go);
            *(uint4*)(dsm + K4_B_LO + so_) = *(const uint4*)(g_b2l + go);
        }
        __syncthreads();

#pragma unroll
        for (int ks = 0; ks < 4; ks++) {
            int k0 = ks * 16;
            uint32_t ah[4], al[4];
            {
                int row = wm + rr + (qq & 1) * 8;
                int col = k0 + (qq >> 1) * 8;
                uint32_t ad = sb + K4_A_HI + (uint32_t)(row * 144 + col * 2);
                ldsm4(ah, ad);
                ldsm4(al, ad + (K4_A_LO - K4_A_HI));
            }
#pragma unroll
            for (int p = 0; p < 8; p++) {
                uint32_t bh4[4], bl4[4];
                int noff = 16 * p + rr + (qq >> 1) * 8;
                int col = k0 + (qq & 1) * 8;
                uint32_t bd = sb + K4_B_HI + (uint32_t)(noff * 144 + col * 2);
                ldsm4(bh4, bd);
                ldsm4(bl4, bd + (K4_B_LO - K4_B_HI));
                mma16816(acc2[2 * p], ah, bh4);
                mma16816(acc2[2 * p + 1], ah, bh4 + 2);
                mma16816(acc2[2 * p], al, bh4);
                mma16816(acc2[2 * p + 1], al, bh4 + 2);
                mma16816(acc2[2 * p], ah, bl4);
                mma16816(acc2[2 * p + 1], ah, bl4 + 2);
            }
        }
        __syncthreads();
    }

    int r0 = lane >> 2, cp = (lane & 3) * 2;
    int mA = m0 + wm + r0, mB = mA + 8;
#pragma unroll
    for (int nt = 0; nt < 16; nt++) {
        int c0 = nt * 8 + cp;
        float b0v = __ldg(&bu2[c0]) + __ldg(&bsc[c0]);
        float b1v = __ldg(&bu2[c0 + 1]) + __ldg(&bsc[c0 + 1]);
        if (mA < MPTS)
            *(float2*)(out + (size_t)mA * 128 + c0) =
                make_float2(lrelu_f(acc2[nt][0] + b0v), lrelu_f(acc2[nt][1] + b1v));
        if (mB < MPTS)
            *(float2*)(out + (size_t)mB * 128 + c0) =
                make_float2(lrelu_f(acc2[nt][2] + b0v), lrelu_f(acc2[nt][3] + b1v));
    }
}

// ======================= launch ============================================
extern "C" void kernel_launch(void* const* d_in, const int* in_sizes, int n_in,
                              void* d_out, int out_size) {
    const float* df  = (const float*)d_in[1];
    const float* vi  = (const float*)d_in[5];
    const int*   nei = (const int*)d_in[6];
    const float* w1  = (const float*)d_in[7];
    const float* b1  = (const float*)d_in[8];
    const float* wgu = (const float*)d_in[9];
    const float* bgu = (const float*)d_in[10];
    const float* wpe = (const float*)d_in[11];
    const float* bpe = (const float*)d_in[12];
    const float* wg1 = (const float*)d_in[13];
    const float* bg1 = (const float*)d_in[14];
    const float* wg2 = (const float*)d_in[15];
    const float* bg2 = (const float*)d_in[16];
    const float* wn1 = (const float*)d_in[17];
    const float* bn1 = (const float*)d_in[18];
    const float* wn2 = (const float*)d_in[19];
    const float* bn2 = (const float*)d_in[20];
    const float* wn3 = (const float*)d_in[21];
    const float* bn3 = (const float*)d_in[22];
    const float* wlin = (const float*)d_in[23];
    const float* blin = (const float*)d_in[24];
    const float* wu2 = (const float*)d_in[25];
    const float* bu2 = (const float*)d_in[26];
    const float* wsc = (const float*)d_in[27];
    const float* bsc = (const float*)d_in[28];
    float* out = (float*)d_out;

    cudaFuncSetAttribute(k34_out, cudaFuncAttributeMaxDynamicSharedMemorySize, K34_SMEM);

    kfront<<<NB_FRONT, 256>>>(df, vi, nei, w1, b1, wgu, bgu, wpe, bpe, wg1,
                              wn1, bn1, wn2, bn2, wn3, bn3, wlin, wu2, wsc);
    k2_point<<<MPTS / 8, 256>>>(nei, wg1, bg1, wg2, bg2);
    k34_out<<<(MPTS + 127) / 128, 256, K34_SMEM>>>(blin, bu2, bsc, out);
}

// round 16
// speedup vs baseline: 1.1073x; 1.1073x over previous
#include <cuda_runtime.h>
#include <cuda_bf16.h>
#include <cuda_fp16.h>
#include <math.h>
#include <stdint.h>

#define NPTS 200000
#define MPTS 100000

// ---------------- scratch (device globals: allocation-free rule) ----------
__device__ float g_fx[NPTS * 32];
__device__ float g_gx[NPTS * 32];
__device__ float g_gw1[NPTS * 8];
__device__ float g_pemax[MPTS * 32];
__device__ float g_pw1[(size_t)MPTS * 16 * 8];
__device__ float g_w[(size_t)MPTS * 16 * 16];
__device__ __half g_agg[(size_t)MPTS * 512];   // fp16 single  102.4 MB
__device__ __half g_sf16[MPTS * 64];           // fp16 single
__device__ __half g_bh16[64 * 512];            // wlin^T fp16 hi [n][k]
__device__ __half g_bl16[64 * 512];            // fp16 lo
__device__ __half g_b2h16[128 * 128];          // [wu2;wsc]^T fp16 hi
__device__ __half g_b2l16[128 * 128];          // fp16 lo

__device__ __forceinline__ float relu_f(float x) { return x > 0.f ? x : 0.f; }
__device__ __forceinline__ float lrelu_f(float x) { return x > 0.f ? x : 0.1f * x; }

__device__ __forceinline__ uint32_t smem_u32(const void* p) {
    uint32_t a;
    asm("{ .reg .u64 t; cvta.to.shared.u64 t, %1; cvt.u32.u64 %0, t; }" : "=r"(a) : "l"(p));
    return a;
}
__device__ __forceinline__ void ldsm4(uint32_t* r, uint32_t a) {
    asm volatile("ldmatrix.sync.aligned.m8n8.x4.shared.b16 {%0,%1,%2,%3}, [%4];"
                 : "=r"(r[0]), "=r"(r[1]), "=r"(r[2]), "=r"(r[3]) : "r"(a));
}
__device__ __forceinline__ void mma16816h(float* d, const uint32_t* a, const uint32_t* b) {
    asm volatile(
        "mma.sync.aligned.m16n8k16.row.col.f32.f16.f16.f32 "
        "{%0,%1,%2,%3}, {%4,%5,%6,%7}, {%8,%9}, {%0,%1,%2,%3};"
        : "+f"(d[0]), "+f"(d[1]), "+f"(d[2]), "+f"(d[3])
        : "r"(a[0]), "r"(a[1]), "r"(a[2]), "r"(a[3]), "r"(b[0]), "r"(b[1]));
}
__device__ __forceinline__ void cp16(uint32_t dst, const void* src) {
    asm volatile("cp.async.cg.shared.global [%0], [%1], 16;" :: "r"(dst), "l"(src));
}
#define CP_COMMIT() asm volatile("cp.async.commit_group;" ::: "memory")
#define CP_WAIT1() asm volatile("cp.async.wait_group 1;" ::: "memory")
#define CP_WAIT0() asm volatile("cp.async.wait_group 0;" ::: "memory")

__device__ __forceinline__ uint32_t packh2(float x, float y) {
    __half2 h = __floats2half2_rn(x, y);
    return *(uint32_t*)&h;
}

// ======================= K0: weight conversions (fp16 hi/lo) ===============
__global__ void __launch_bounds__(256) k0_wconv(
    const float* __restrict__ wlin, const float* __restrict__ wu2,
    const float* __restrict__ wsc) {
    int i = blockIdx.x * 256 + threadIdx.x;
    if (i < 512 * 64) {
        int n = i >> 9, k = i & 511;
        float v = __ldg(&wlin[k * 64 + n]);
        __half h = __float2half_rn(v);
        g_bh16[i] = h;
        g_bl16[i] = __float2half_rn(v - __half2float(h));
    }
    if (i < 128 * 128) {
        int n = i >> 7, k = i & 127;
        float v = (k < 64) ? __ldg(&wu2[k * 128 + n]) : __ldg(&wsc[(k - 64) * 128 + n]);
        __half h = __float2half_rn(v);
        g_b2h16[i] = h;
        g_b2l16[i] = __float2half_rn(v - __half2float(h));
    }
}

// ======================= K1: dense transform + gw1 =========================
__global__ void __launch_bounds__(256) k1_dense(
    const float* __restrict__ df,
    const float* __restrict__ w1, const float* __restrict__ b1,
    const float* __restrict__ wgu, const float* __restrict__ bgu,
    const float* __restrict__ wg1) {
    __shared__ __align__(16) float s_w1[64 * 32];
    __shared__ __align__(16) float s_wgu[32 * 32];
    __shared__ __align__(16) float s_wg1k[32 * 8];
    __shared__ union {
        float f[128][68];
        float fx[128][36];
    } u;
    int t = threadIdx.x;
    int p0 = blockIdx.x * 128;
    for (int i = t; i < 2048; i += 256) s_w1[i] = w1[i];
    for (int i = t; i < 1024; i += 256) s_wgu[i] = wgu[i];
    if (t < 256) s_wg1k[t] = wg1[t];
#pragma unroll
    for (int q = 0; q < 8; q++) {
        int id = t + q * 256;
        int pp = id >> 4, kk = (id & 15) * 4;
        int gm = p0 + pp; if (gm >= NPTS) gm = NPTS - 1;
        *(float4*)&u.f[pp][kk] = *(const float4*)(df + (size_t)gm * 64 + kk);
    }
    __syncthreads();

    int pg = t >> 3, cg = t & 7;
    int c4 = cg * 4;
    float4 bb = *(const float4*)(b1 + c4);
    float acc[4][4];
#pragma unroll
    for (int i = 0; i < 4; i++) { acc[i][0] = bb.x; acc[i][1] = bb.y; acc[i][2] = bb.z; acc[i][3] = bb.w; }
#pragma unroll
    for (int kb = 0; kb < 64; kb += 4) {
        float4 a[4];
#pragma unroll
        for (int i = 0; i < 4; i++) a[i] = *(const float4*)&u.f[pg * 4 + i][kb];
#pragma unroll
        for (int q = 0; q < 4; q++) {
            float4 w = *(const float4*)&s_w1[(kb + q) * 32 + c4];
#pragma unroll
            for (int i = 0; i < 4; i++) {
                float av = q == 0 ? a[i].x : q == 1 ? a[i].y : q == 2 ? a[i].z : a[i].w;
                acc[i][0] = fmaf(av, w.x, acc[i][0]); acc[i][1] = fmaf(av, w.y, acc[i][1]);
                acc[i][2] = fmaf(av, w.z, acc[i][2]); acc[i][3] = fmaf(av, w.w, acc[i][3]);
            }
        }
    }
    float4 fxv[4];
#pragma unroll
    for (int i = 0; i < 4; i++)
        fxv[i] = make_float4(lrelu_f(acc[i][0]), lrelu_f(acc[i][1]), lrelu_f(acc[i][2]), lrelu_f(acc[i][3]));
    __syncthreads();
#pragma unroll
    for (int i = 0; i < 4; i++) {
        int gm = p0 + pg * 4 + i;
        *(float4*)&u.fx[pg * 4 + i][c4] = fxv[i];
        if (gm < NPTS) *(float4*)(g_fx + (size_t)gm * 32 + c4) = fxv[i];
    }
    __syncthreads();

    float4 bg = *(const float4*)(bgu + c4);
    float gac[4][4];
#pragma unroll
    for (int i = 0; i < 4; i++) { gac[i][0] = bg.x; gac[i][1] = bg.y; gac[i][2] = bg.z; gac[i][3] = bg.w; }
#pragma unroll
    for (int kb = 0; kb < 32; kb += 4) {
        float4 a[4];
#pragma unroll
        for (int i = 0; i < 4; i++) a[i] = *(const float4*)&u.fx[pg * 4 + i][kb];
#pragma unroll
        for (int q = 0; q < 4; q++) {
            float4 w = *(const float4*)&s_wgu[(kb + q) * 32 + c4];
#pragma unroll
            for (int i = 0; i < 4; i++) {
                float av = q == 0 ? a[i].x : q == 1 ? a[i].y : q == 2 ? a[i].z : a[i].w;
                gac[i][0] = fmaf(av, w.x, gac[i][0]); gac[i][1] = fmaf(av, w.y, gac[i][1]);
                gac[i][2] = fmaf(av, w.z, gac[i][2]); gac[i][3] = fmaf(av, w.w, gac[i][3]);
            }
        }
    }
    __syncthreads();
#pragma unroll
    for (int i = 0; i < 4; i++) {
        int gm = p0 + pg * 4 + i;
        *(float4*)&u.fx[pg * 4 + i][c4] =
            make_float4(gac[i][0], gac[i][1], gac[i][2], gac[i][3]);
        if (gm < NPTS)
            *(float4*)(g_gx + (size_t)gm * 32 + c4) =
                make_float4(gac[i][0], gac[i][1], gac[i][2], gac[i][3]);
    }
    __syncthreads();

    {
        int p2 = t >> 1, h4 = (t & 1) * 4;
        float o4[4] = {0.f, 0.f, 0.f, 0.f};
#pragma unroll
        for (int c = 0; c < 32; c++) {
            float g = u.fx[p2][c];
            float4 w = *(const float4*)&s_wg1k[c * 8 + h4];
            o4[0] = fmaf(g, w.x, o4[0]); o4[1] = fmaf(g, w.y, o4[1]);
            o4[2] = fmaf(g, w.z, o4[2]); o4[3] = fmaf(g, w.w, o4[3]);
        }
        int gm = p0 + p2;
        if (gm < NPTS)
            *(float4*)(g_gw1 + (size_t)gm * 8 + h4) = make_float4(o4[0], o4[1], o4[2], o4[3]);
    }
}

// ======================= K6: dense PE/WeightNet + pe channel-max ===========
__global__ void __launch_bounds__(256) k6_pewn(
    const float* __restrict__ vi_f,
    const float* __restrict__ wpe, const float* __restrict__ bpe,
    const float* __restrict__ wg1,
    const float* __restrict__ wn1, const float* __restrict__ bn1,
    const float* __restrict__ wn2, const float* __restrict__ bn2,
    const float* __restrict__ wn3, const float* __restrict__ bn3) {
    __shared__ __align__(16) float s_wpet[32 * 12];
    __shared__ __align__(16) float s_w1h[32 * 8];
    __shared__ __align__(16) float s_wn1t[8 * 12];
    __shared__ __align__(16) float s_wn2t[8 * 8];
    __shared__ __align__(16) float s_wn3t[16 * 8];
    __shared__ float s_bpe[32], s_bn1[8], s_bn2[8], s_bn3[16];
    __shared__ __align__(16) float s_tmp[256][36];
    int t = threadIdx.x;
    for (int i = t; i < 384; i += 256) { int c = i / 12, ii = i % 12; s_wpet[i] = wpe[ii * 32 + c]; }
    if (t < 256) s_w1h[t] = wg1[256 + t];
    if (t < 96) { int o = t / 12, ii = t % 12; s_wn1t[t] = wn1[ii * 8 + o]; }
    if (t < 64) s_wn2t[t] = wn2[(t & 7) * 8 + (t >> 3)];
    if (t < 128) { int o = t >> 3, ii = t & 7; s_wn3t[t] = wn3[ii * 16 + o]; }
    if (t < 32) s_bpe[t] = bpe[t];
    if (t < 8) { s_bn1[t] = bn1[t]; s_bn2[t] = bn2[t]; }
    if (t < 16) s_bn3[t] = bn3[t];
    __syncthreads();

    size_t r0 = (size_t)blockIdx.x * 512 + t * 2;
    float va[12], vb[12];
    {
        const float4* p = (const float4*)(vi_f + r0 * 12);
        float4 x0 = p[0], x1 = p[1], x2 = p[2], x3 = p[3], x4 = p[4], x5 = p[5];
        va[0] = x0.x; va[1] = x0.y; va[2] = x0.z; va[3] = x0.w;
        va[4] = x1.x; va[5] = x1.y; va[6] = x1.z; va[7] = x1.w;
        va[8] = x2.x; va[9] = x2.y; va[10] = x2.z; va[11] = x2.w;
        vb[0] = x3.x; vb[1] = x3.y; vb[2] = x3.z; vb[3] = x3.w;
        vb[4] = x4.x; vb[5] = x4.y; vb[6] = x4.z; vb[7] = x4.w;
        vb[8] = x5.x; vb[9] = x5.y; vb[10] = x5.z; vb[11] = x5.w;
    }

    float pwa[8], pwb[8];
#pragma unroll
    for (int h = 0; h < 8; h++) { pwa[h] = 0.f; pwb[h] = 0.f; }
#pragma unroll
    for (int c = 0; c < 32; c++) {
        const float4* wr = (const float4*)&s_wpet[c * 12];
        float4 w0 = wr[0], w1v = wr[1], w2 = wr[2];
        float bias = s_bpe[c];
        float a = bias, b = bias;
        a = fmaf(va[0], w0.x, a);  b = fmaf(vb[0], w0.x, b);
        a = fmaf(va[1], w0.y, a);  b = fmaf(vb[1], w0.y, b);
        a = fmaf(va[2], w0.z, a);  b = fmaf(vb[2], w0.z, b);
        a = fmaf(va[3], w0.w, a);  b = fmaf(vb[3], w0.w, b);
        a = fmaf(va[4], w1v.x, a); b = fmaf(vb[4], w1v.x, b);
        a = fmaf(va[5], w1v.y, a); b = fmaf(vb[5], w1v.y, b);
        a = fmaf(va[6], w1v.z, a); b = fmaf(vb[6], w1v.z, b);
        a = fmaf(va[7], w1v.w, a); b = fmaf(vb[7], w1v.w, b);
        a = fmaf(va[8], w2.x, a);  b = fmaf(vb[8], w2.x, b);
        a = fmaf(va[9], w2.y, a);  b = fmaf(vb[9], w2.y, b);
        a = fmaf(va[10], w2.z, a); b = fmaf(vb[10], w2.z, b);
        a = fmaf(va[11], w2.w, a); b = fmaf(vb[11], w2.w, b);
        float ra = relu_f(a), rb = relu_f(b);
        s_tmp[t][c] = fmaxf(ra, rb);
        const float4* wh = (const float4*)&s_w1h[c * 8];
        float4 ha = wh[0], hb = wh[1];
        pwa[0] = fmaf(ra, ha.x, pwa[0]); pwa[1] = fmaf(ra, ha.y, pwa[1]);
        pwa[2] = fmaf(ra, ha.z, pwa[2]); pwa[3] = fmaf(ra, ha.w, pwa[3]);
        pwa[4] = fmaf(ra, hb.x, pwa[4]); pwa[5] = fmaf(ra, hb.y, pwa[5]);
        pwa[6] = fmaf(ra, hb.z, pwa[6]); pwa[7] = fmaf(ra, hb.w, pwa[7]);
        pwb[0] = fmaf(rb, ha.x, pwb[0]); pwb[1] = fmaf(rb, ha.y, pwb[1]);
        pwb[2] = fmaf(rb, ha.z, pwb[2]); pwb[3] = fmaf(rb, ha.w, pwb[3]);
        pwb[4] = fmaf(rb, hb.x, pwb[4]); pwb[5] = fmaf(rb, hb.y, pwb[5]);
        pwb[6] = fmaf(rb, hb.z, pwb[6]); pwb[7] = fmaf(rb, hb.w, pwb[7]);
    }
    *(float4*)(g_pw1 + r0 * 8) = make_float4(pwa[0], pwa[1], pwa[2], pwa[3]);
    *(float4*)(g_pw1 + r0 * 8 + 4) = make_float4(pwa[4], pwa[5], pwa[6], pwa[7]);
    *(float4*)(g_pw1 + (r0 + 1) * 8) = make_float4(pwb[0], pwb[1], pwb[2], pwb[3]);
    *(float4*)(g_pw1 + (r0 + 1) * 8 + 4) = make_float4(pwb[4], pwb[5], pwb[6], pwb[7]);

    float h1a[8], h1b[8];
#pragma unroll
    for (int o = 0; o < 8; o++) {
        const float4* wr = (const float4*)&s_wn1t[o * 12];
        float4 w0 = wr[0], w1v = wr[1], w2 = wr[2];
        float bias = s_bn1[o];
        float a = bias, b = bias;
        a = fmaf(va[0], w0.x, a);  b = fmaf(vb[0], w0.x, b);
        a = fmaf(va[1], w0.y, a);  b = fmaf(vb[1], w0.y, b);
        a = fmaf(va[2], w0.z, a);  b = fmaf(vb[2], w0.z, b);
        a = fmaf(va[3], w0.w, a);  b = fmaf(vb[3], w0.w, b);
        a = fmaf(va[4], w1v.x, a); b = fmaf(vb[4], w1v.x, b);
        a = fmaf(va[5], w1v.y, a); b = fmaf(vb[5], w1v.y, b);
        a = fmaf(va[6], w1v.z, a); b = fmaf(vb[6], w1v.z, b);
        a = fmaf(va[7], w1v.w, a); b = fmaf(vb[7], w1v.w, b);
        a = fmaf(va[8], w2.x, a);  b = fmaf(vb[8], w2.x, b);
        a = fmaf(va[9], w2.y, a);  b = fmaf(vb[9], w2.y, b);
        a = fmaf(va[10], w2.z, a); b = fmaf(vb[10], w2.z, b);
        a = fmaf(va[11], w2.w, a); b = fmaf(vb[11], w2.w, b);
        h1a[o] = relu_f(a); h1b[o] = relu_f(b);
    }
    float h2a[8], h2b[8];
#pragma unroll
    for (int o = 0; o < 8; o++) {
        const float4* wr = (const float4*)&s_wn2t[o * 8];
        float4 wx = wr[0], wy = wr[1];
        float bias = s_bn2[o];
        float a = bias, b = bias;
        a = fmaf(h1a[0], wx.x, a); b = fmaf(h1b[0], wx.x, b);
        a = fmaf(h1a[1], wx.y, a); b = fmaf(h1b[1], wx.y, b);
        a = fmaf(h1a[2], wx.z, a); b = fmaf(h1b[2], wx.z, b);
        a = fmaf(h1a[3], wx.w, a); b = fmaf(h1b[3], wx.w, b);
        a = fmaf(h1a[4], wy.x, a); b = fmaf(h1b[4], wy.x, b);
        a = fmaf(h1a[5], wy.y, a); b = fmaf(h1b[5], wy.y, b);
        a = fmaf(h1a[6], wy.z, a); b = fmaf(h1b[6], wy.z, b);
        a = fmaf(h1a[7], wy.w, a); b = fmaf(h1b[7], wy.w, b);
        h2a[o] = relu_f(a); h2b[o] = relu_f(b);
    }
    float pa[4], pb[4];
#pragma unroll
    for (int o = 0; o < 16; o++) {
        const float4* wr = (const float4*)&s_wn3t[o * 8];
        float4 wx = wr[0], wy = wr[1];
        float bias = s_bn3[o];
        float a = bias, b = bias;
        a = fmaf(h2a[0], wx.x, a); b = fmaf(h2b[0], wx.x, b);
        a = fmaf(h2a[1], wx.y, a); b = fmaf(h2b[1], wx.y, b);
        a = fmaf(h2a[2], wx.z, a); b = fmaf(h2b[2], wx.z, b);
        a = fmaf(h2a[3], wx.w, a); b = fmaf(h2b[3], wx.w, b);
        a = fmaf(h2a[4], wy.x, a); b = fmaf(h2b[4], wy.x, b);
        a = fmaf(h2a[5], wy.y, a); b = fmaf(h2b[5], wy.y, b);
        a = fmaf(h2a[6], wy.z, a); b = fmaf(h2b[6], wy.z, b);
        a = fmaf(h2a[7], wy.w, a); b = fmaf(h2b[7], wy.w, b);
        pa[o & 3] = relu_f(a); pb[o & 3] = relu_f(b);
        if ((o & 3) == 3) {
            *(float4*)(g_w + r0 * 16 + (o - 3)) = make_float4(pa[0], pa[1], pa[2], pa[3]);
            *(float4*)(g_w + (r0 + 1) * 16 + (o - 3)) = make_float4(pb[0], pb[1], pb[2], pb[3]);
        }
    }

    __syncthreads();
    int pt = t >> 3, ch0 = (t & 7) * 4;
    int base = pt * 8;
    float4 vm = *(const float4*)&s_tmp[base][ch0];
#pragma unroll
    for (int k = 1; k < 8; k++) {
        float4 v = *(const float4*)&s_tmp[base + k][ch0];
        vm.x = fmaxf(vm.x, v.x); vm.y = fmaxf(vm.y, v.y);
        vm.z = fmaxf(vm.z, v.z); vm.w = fmaxf(vm.w, v.w);
    }
    *(float4*)(g_pemax + (size_t)(blockIdx.x * 32 + pt) * 32 + ch0) = vm;
}

// ======================= K5: shortcut maxpool (fp16 out) ===================
__global__ void __launch_bounds__(256) k5_maxpool(
    const float* __restrict__ df, const int* __restrict__ nei) {
    const unsigned FULL = 0xffffffffu;
    int t = threadIdx.x;
    int wid = t >> 5, lane = t & 31;
    int m = blockIdx.x * 8 + wid;
    int j = lane >> 1;
    int idx = __ldg(&nei[m * 16 + j]);
    float m0v = -3.0e38f, m1v = -3.0e38f;
#pragma unroll
    for (int jj = 0; jj < 16; jj++) {
        int ix = __shfl_sync(FULL, idx, jj * 2);
        m0v = fmaxf(m0v, __ldg(&df[(size_t)ix * 64 + lane]));
        m1v = fmaxf(m1v, __ldg(&df[(size_t)ix * 64 + 32 + lane]));
    }
    g_sf16[(size_t)m * 64 + lane] = __float2half_rn(m0v);
    g_sf16[(size_t)m * 64 + 32 + lane] = __float2half_rn(m1v);
}

// ======================= K2: gather + attention + agg ======================
__global__ void __launch_bounds__(256, 2) k2_point(
    const int* __restrict__ nei,
    const float* __restrict__ wg1, const float* __restrict__ bg1,
    const float* __restrict__ wg2, const float* __restrict__ bg2) {
    __shared__ __align__(16) float s_wg1[64 * 8];
    __shared__ __align__(16) float s_wg2t[8 * 8];
    __shared__ float s_bg1[8], s_bg2[8];
    __shared__ __align__(16) float s_gf[8][16][36];
    __shared__ __align__(16) float s_nf[8][16][36];
    __shared__ __align__(16) float s_w[8][16][20];
    int t = threadIdx.x;
    for (int i = t; i < 512; i += 256) s_wg1[i] = wg1[i];
    if (t < 64) s_wg2t[t] = wg2[(t & 7) * 8 + (t >> 3)];
    if (t < 8) { s_bg1[t] = bg1[t]; s_bg2[t] = bg2[t]; }
    __syncthreads();

    const unsigned FULL = 0xffffffffu;
    int wid = t >> 5, lane = t & 31;
    int j = lane >> 1, half = lane & 1;
    int m = blockIdx.x * 8 + wid;
    int idx = __ldg(&nei[m * 16 + j]);
    size_t row = (size_t)m * 16 + j;

    {
        const char* gsrc = (const char*)(g_gx + (size_t)idx * 32 + half * 16);
        uint32_t gdst = smem_u32(&s_gf[wid][j][half * 16]);
        cp16(gdst, gsrc); cp16(gdst + 16, gsrc + 16);
        cp16(gdst + 32, gsrc + 32); cp16(gdst + 48, gsrc + 48);
        const char* fsrc = (const char*)(g_fx + (size_t)idx * 32 + half * 16);
        uint32_t fdst = smem_u32(&s_nf[wid][j][half * 16]);
        cp16(fdst, fsrc); cp16(fdst + 16, fsrc + 16);
        cp16(fdst + 32, fsrc + 32); cp16(fdst + 48, fsrc + 48);
        const char* wsrc = (const char*)(g_w + row * 16 + half * 8);
        uint32_t wdst = smem_u32(&s_w[wid][j][half * 8]);
        cp16(wdst, wsrc); cp16(wdst + 16, wsrc + 16);
        CP_COMMIT();
    }
    float part[8];
    {
        const float* psrc = half ? (g_pw1 + row * 8) : (g_gw1 + (size_t)idx * 8);
        float4 a0 = __ldg((const float4*)psrc);
        float4 a1 = __ldg((const float4*)(psrc + 4));
        part[0] = a0.x; part[1] = a0.y; part[2] = a0.z; part[3] = a0.w;
        part[4] = a1.x; part[5] = a1.y; part[6] = a1.z; part[7] = a1.w;
    }
    float mx1 = __ldg(&g_pemax[(size_t)m * 32 + lane]);

    CP_WAIT0();
    __syncwarp();

    float mx0 = -3.0e38f;
    int cl = lane;
#pragma unroll
    for (int jj = 0; jj < 16; jj++)
        mx0 = fmaxf(mx0, s_gf[wid][jj][cl]);
    float mw[8];
    {
        const float4* wr0 = (const float4*)&s_wg1[cl * 8];
        const float4* wr1 = (const float4*)&s_wg1[(cl + 32) * 8];
        float4 a0 = wr0[0], a1 = wr0[1], b0 = wr1[0], b1v = wr1[1];
        mw[0] = fmaf(mx0, a0.x, mx1 * b0.x); mw[1] = fmaf(mx0, a0.y, mx1 * b0.y);
        mw[2] = fmaf(mx0, a0.z, mx1 * b0.z); mw[3] = fmaf(mx0, a0.w, mx1 * b0.w);
        mw[4] = fmaf(mx0, a1.x, mx1 * b1v.x); mw[5] = fmaf(mx0, a1.y, mx1 * b1v.y);
        mw[6] = fmaf(mx0, a1.z, mx1 * b1v.z); mw[7] = fmaf(mx0, a1.w, mx1 * b1v.w);
    }
#pragma unroll
    for (int s = 16; s >= 1; s >>= 1) {
#pragma unroll
        for (int h = 0; h < 8; h++) mw[h] += __shfl_xor_sync(FULL, mw[h], s);
    }
#pragma unroll
    for (int h = 0; h < 8; h++) part[h] += __shfl_xor_sync(FULL, part[h], 1);

    float s1v[8];
#pragma unroll
    for (int h = 0; h < 8; h++) s1v[h] = relu_f(part[h] - mw[h] + s_bg1[h]);
    float sc4[4];
#pragma unroll
    for (int hq = 0; hq < 4; hq++) {
        int h2 = half * 4 + hq;
        float a = s_bg2[h2];
        const float4* wr = (const float4*)&s_wg2t[h2 * 8];
        float4 wa = wr[0], wb = wr[1];
        a = fmaf(s1v[0], wa.x, a); a = fmaf(s1v[1], wa.y, a);
        a = fmaf(s1v[2], wa.z, a); a = fmaf(s1v[3], wa.w, a);
        a = fmaf(s1v[4], wb.x, a); a = fmaf(s1v[5], wb.y, a);
        a = fmaf(s1v[6], wb.z, a); a = fmaf(s1v[7], wb.w, a);
        sc4[hq] = 1.f / (1.f + __expf(-a));
    }

#pragma unroll
    for (int q = 0; q < 4; q++) {
        int c0 = half * 16 + 4 * q;
        float4 v = *(const float4*)&s_nf[wid][j][c0];
        float s = sc4[q];
        *(float4*)&s_nf[wid][j][c0] = make_float4(v.x * s, v.y * s, v.z * s, v.w * s);
    }
    __syncwarp();

    float acc[16];
#pragma unroll
    for (int w = 0; w < 16; w++) acc[w] = 0.f;
    int c = lane;
#pragma unroll
    for (int jj = 0; jj < 16; jj++) {
        float a = s_nf[wid][jj][c];
        const float4* wp = (const float4*)&s_w[wid][jj][0];
        float4 w0 = wp[0], w1v = wp[1], w2 = wp[2], w3 = wp[3];
        acc[0] = fmaf(a, w0.x, acc[0]);  acc[1] = fmaf(a, w0.y, acc[1]);
        acc[2] = fmaf(a, w0.z, acc[2]);  acc[3] = fmaf(a, w0.w, acc[3]);
        acc[4] = fmaf(a, w1v.x, acc[4]); acc[5] = fmaf(a, w1v.y, acc[5]);
        acc[6] = fmaf(a, w1v.z, acc[6]); acc[7] = fmaf(a, w1v.w, acc[7]);
        acc[8] = fmaf(a, w2.x, acc[8]);  acc[9] = fmaf(a, w2.y, acc[9]);
        acc[10] = fmaf(a, w2.z, acc[10]); acc[11] = fmaf(a, w2.w, acc[11]);
        acc[12] = fmaf(a, w3.x, acc[12]); acc[13] = fmaf(a, w3.y, acc[13]);
        acc[14] = fmaf(a, w3.z, acc[14]); acc[15] = fmaf(a, w3.w, acc[15]);
    }
    // store agg as fp16 single (coalesced 32B per lane)
    __align__(16) __half hb[16];
#pragma unroll
    for (int w = 0; w < 16; w++) hb[w] = __float2half_rn(acc[w]);
    size_t bo = (size_t)m * 512 + c * 16;
    ((uint4*)(g_agg + bo))[0] = ((uint4*)hb)[0];
    ((uint4*)(g_agg + bo))[1] = ((uint4*)hb)[1];
}

// ======================= K34: fused GEMM1 + GEMM2 (fp16 A) =================
// smem layout:
//   phase1: A (2 stages x 18432) @0; B_HI (2 x 9216) @36864; B_LO @55296
//   phase2: o f32 [128][65] @0; A2 fp16 @36864; B2_HI @55296; B2_LO @73728
#define K3_A    0u
#define K3_B_HI 36864u
#define K3_B_LO 55296u
#define K4_A2   36864u
#define K4_B_HI 55296u
#define K4_B_LO 73728u
#define K34_SMEM 92160

__device__ __forceinline__ void k3_load(uint32_t sb, int t, int m0, int kt, int st) {
    uint32_t aofs = (uint32_t)st * 18432u;
    uint32_t bofs = (uint32_t)st * 9216u;
#pragma unroll
    for (int q = 0; q < 4; q++) {
        int id = t + q * 256;
        int row = id >> 3, seg = id & 7;
        int gm = m0 + row; if (gm >= MPTS) gm = MPTS - 1;
        size_t go = (size_t)gm * 512 + kt * 64 + seg * 8;
        uint32_t so_ = (uint32_t)(row * 144 + seg * 16);
        cp16(sb + K3_A + aofs + so_, g_agg + go);
    }
#pragma unroll
    for (int q = 0; q < 2; q++) {
        int id = t + q * 256;
        int n = id >> 3, seg = id & 7;
        size_t go = (size_t)n * 512 + kt * 64 + seg * 8;
        uint32_t so_ = (uint32_t)(n * 144 + seg * 16);
        cp16(sb + K3_B_HI + bofs + so_, g_bh16 + go);
        cp16(sb + K3_B_LO + bofs + so_, g_bl16 + go);
    }
}

__global__ void __launch_bounds__(256, 2) k34_out(
    const float* __restrict__ blin,
    const float* __restrict__ bu2, const float* __restrict__ bsc,
    float* __restrict__ out) {
    extern __shared__ __align__(16) char dsm[];
    uint32_t sb = smem_u32(dsm);
    int t = threadIdx.x;
    int wid = t >> 5, lane = t & 31;
    int m0 = blockIdx.x * 128;
    int wm = wid * 16;
    int qq = lane >> 3, rr = lane & 7;

    // ---------------- Phase 1: GEMM1 ----------------
    {
        float acc[8][4];
#pragma unroll
        for (int nt = 0; nt < 8; nt++)
#pragma unroll
            for (int q = 0; q < 4; q++) acc[nt][q] = 0.f;

        k3_load(sb, t, m0, 0, 0);
        CP_COMMIT();

#pragma unroll 1
        for (int kt = 0; kt < 8; kt++) {
            int st = kt & 1;
            if (kt < 7) {
                k3_load(sb, t, m0, kt + 1, st ^ 1);
                CP_COMMIT();
                CP_WAIT1();
            } else {
                CP_WAIT0();
            }
            __syncthreads();

            uint32_t aofs = (uint32_t)st * 18432u;
            uint32_t bofs = (uint32_t)st * 9216u;
#pragma unroll
            for (int ks = 0; ks < 4; ks++) {
                int k0 = ks * 16;
                uint32_t ah[4];
                {
                    int row = wm + rr + (qq & 1) * 8;
                    int col = k0 + (qq >> 1) * 8;
                    ldsm4(ah, sb + K3_A + aofs + (uint32_t)(row * 144 + col * 2));
                }
#pragma unroll
                for (int p = 0; p < 4; p++) {
                    uint32_t bh4[4], bl4[4];
                    int noff = 16 * p + rr + (qq >> 1) * 8;
                    int col = k0 + (qq & 1) * 8;
                    uint32_t bd = sb + K3_B_HI + bofs + (uint32_t)(noff * 144 + col * 2);
                    ldsm4(bh4, bd);
                    ldsm4(bl4, bd + (K3_B_LO - K3_B_HI));
                    mma16816h(acc[2 * p], ah, bh4);
                    mma16816h(acc[2 * p + 1], ah, bh4 + 2);
                    mma16816h(acc[2 * p], ah, bl4);
                    mma16816h(acc[2 * p + 1], ah, bl4 + 2);
                }
            }
            __syncthreads();
        }

        {
            int rrow = lane >> 2, cp = (lane & 3) * 2;
            float* so = (float*)dsm;
#pragma unroll
            for (int nt = 0; nt < 8; nt++) {
                int c0 = nt * 8 + cp;
                float b0v = __ldg(&blin[c0]), b1v = __ldg(&blin[c0 + 1]);
                so[(wm + rrow) * 65 + c0]         = relu_f(acc[nt][0] + b0v);
                so[(wm + rrow) * 65 + c0 + 1]     = relu_f(acc[nt][1] + b1v);
                so[(wm + rrow + 8) * 65 + c0]     = relu_f(acc[nt][2] + b0v);
                so[(wm + rrow + 8) * 65 + c0 + 1] = relu_f(acc[nt][3] + b1v);
            }
        }
        __syncthreads();
    }

    // ---------------- Phase 2: GEMM2 + final epilogue ----------------
    float acc2[16][4];
#pragma unroll
    for (int nt = 0; nt < 16; nt++)
#pragma unroll
        for (int q = 0; q < 4; q++) acc2[nt][q] = 0.f;

#pragma unroll 1
    for (int kt = 0; kt < 2; kt++) {
        if (kt == 0) {
            // build A2 fp16 from smem o
            const float* so = (const float*)dsm;
#pragma unroll
            for (int q = 0; q < 4; q++) {
                int id = t + q * 256;
                int row = id >> 3, seg = id & 7;
                const float* src = so + row * 65 + seg * 8;
                uint32_t p0 = packh2(src[0], src[1]);
                uint32_t p1 = packh2(src[2], src[3]);
                uint32_t p2 = packh2(src[4], src[5]);
                uint32_t p3 = packh2(src[6], src[7]);
                asm volatile("st.shared.v4.b32 [%0], {%1,%2,%3,%4};"
                             :: "r"(sb + K4_A2 + (uint32_t)(row * 144 + seg * 16)),
                                "r"(p0), "r"(p1), "r"(p2), "r"(p3) : "memory");
            }
        } else {
#pragma unroll
            for (int q = 0; q < 4; q++) {
                int id = t + q * 256;
                int row = id >> 3, seg = id & 7;
                int gm = m0 + row; if (gm >= MPTS) gm = MPTS - 1;
                *(uint4*)(dsm + K4_A2 + (uint32_t)(row * 144 + seg * 16)) =
                    *(const uint4*)(g_sf16 + (size_t)gm * 64 + seg * 8);
            }
        }
#pragma unroll
        for (int q = 0; q < 4; q++) {
            int id = t + q * 256;
            int n = id >> 3, seg = id & 7;
            size_t go = (size_t)n * 128 + kt * 64 + seg * 8;
            uint32_t so_ = (uint32_t)(n * 144 + seg * 16);
            *(uint4*)(dsm + K4_B_HI + so_) = *(const uint4*)(g_b2h16 + go);
            *(uint4*)(dsm + K4_B_LO + so_) = *(const uint4*)(g_b2l16 + go);
        }
        __syncthreads();

#pragma unroll
        for (int ks = 0; ks < 4; ks++) {
            int k0 = ks * 16;
            uint32_t ah[4];
            {
                int row = wm + rr + (qq & 1) * 8;
                int col = k0 + (qq >> 1) * 8;
                ldsm4(ah, sb + K4_A2 + (uint32_t)(row * 144 + col * 2));
            }
#pragma unroll
            for (int p = 0; p < 8; p++) {
                uint32_t bh4[4], bl4[4];
                int noff = 16 * p + rr + (qq >> 1) * 8;
                int col = k0 + (qq & 1) * 8;
                uint32_t bd = sb + K4_B_HI + (uint32_t)(noff * 144 + col * 2);
                ldsm4(bh4, bd);
                ldsm4(bl4, bd + (K4_B_LO - K4_B_HI));
                mma16816h(acc2[2 * p], ah, bh4);
                mma16816h(acc2[2 * p + 1], ah, bh4 + 2);
                mma16816h(acc2[2 * p], ah, bl4);
                mma16816h(acc2[2 * p + 1], ah, bl4 + 2);
            }
        }
        __syncthreads();
    }

    int r0 = lane >> 2, cp = (lane & 3) * 2;
    int mA = m0 + wm + r0, mB = mA + 8;
#pragma unroll
    for (int nt = 0; nt < 16; nt++) {
        int c0 = nt * 8 + cp;
        float b0v = __ldg(&bu2[c0]) + __ldg(&bsc[c0]);
        float b1v = __ldg(&bu2[c0 + 1]) + __ldg(&bsc[c0 + 1]);
        if (mA < MPTS)
            *(float2*)(out + (size_t)mA * 128 + c0) =
                make_float2(lrelu_f(acc2[nt][0] + b0v), lrelu_f(acc2[nt][1] + b1v));
        if (mB < MPTS)
            *(float2*)(out + (size_t)mB * 128 + c0) =
                make_float2(lrelu_f(acc2[nt][2] + b0v), lrelu_f(acc2[nt][3] + b1v));
    }
}

// ======================= launch ============================================
extern "C" void kernel_launch(void* const* d_in, const int* in_sizes, int n_in,
                              void* d_out, int out_size) {
    const float* df  = (const float*)d_in[1];
    const float* vi  = (const float*)d_in[5];
    const int*   nei = (const int*)d_in[6];
    const float* w1  = (const float*)d_in[7];
    const float* b1  = (const float*)d_in[8];
    const float* wgu = (const float*)d_in[9];
    const float* bgu = (const float*)d_in[10];
    const float* wpe = (const float*)d_in[11];
    const float* bpe = (const float*)d_in[12];
    const float* wg1 = (const float*)d_in[13];
    const float* bg1 = (const float*)d_in[14];
    const float* wg2 = (const float*)d_in[15];
    const float* bg2 = (const float*)d_in[16];
    const float* wn1 = (const float*)d_in[17];
    const float* bn1 = (const float*)d_in[18];
    const float* wn2 = (const float*)d_in[19];
    const float* bn2 = (const float*)d_in[20];
    const float* wn3 = (const float*)d_in[21];
    const float* bn3 = (const float*)d_in[22];
    const float* wlin = (const float*)d_in[23];
    const float* blin = (const float*)d_in[24];
    const float* wu2 = (const float*)d_in[25];
    const float* bu2 = (const float*)d_in[26];
    const float* wsc = (const float*)d_in[27];
    const float* bsc = (const float*)d_in[28];
    float* out = (float*)d_out;

    cudaFuncSetAttribute(k34_out, cudaFuncAttributeMaxDynamicSharedMemorySize, K34_SMEM);

    // k2 kept at launch index 3 (the one ncu captures).
    k0_wconv<<<128, 256>>>(wlin, wu2, wsc);
    k1_dense<<<(NPTS + 127) / 128, 256>>>(df, w1, b1, wgu, bgu, wg1);
    k6_pewn<<<(MPTS * 16) / 512, 256>>>(vi, wpe, bpe, wg1,
                                        wn1, bn1, wn2, bn2, wn3, bn3);
    k2_point<<<MPTS / 8, 256>>>(nei, wg1, bg1, wg2, bg2);
    k5_maxpool<<<MPTS / 8, 256>>>(df, nei);
    k34_out<<<(MPTS + 127) / 128, 256, K34_SMEM>>>(blin, bu2, bsc, out);
}

// round 17
// speedup vs baseline: 1.1591x; 1.0467x over previous
#include <cuda_runtime.h>
#include <cuda_bf16.h>
#include <cuda_fp16.h>
#include <math.h>
#include <stdint.h>

#define NPTS 200000
#define MPTS 100000

// ---------------- scratch (device globals: allocation-free rule) ----------
__device__ float g_fx[NPTS * 32];
__device__ float g_gx[NPTS * 32];
__device__ float g_gw1[NPTS * 8];
__device__ float g_pemax[MPTS * 32];
__device__ __half g_pw116[(size_t)MPTS * 16 * 8];   // pe@W1hi fp16   25.6 MB
__device__ __half g_w16[(size_t)MPTS * 16 * 16];    // WeightNet fp16 51.2 MB
__device__ __half g_agg[(size_t)MPTS * 512];        // fp16 single   102.4 MB
__device__ __half g_sf16[MPTS * 64];
__device__ __half g_bh16[64 * 512];
__device__ __half g_bl16[64 * 512];
__device__ __half g_b2h16[128 * 128];
__device__ __half g_b2l16[128 * 128];

__device__ __forceinline__ float relu_f(float x) { return x > 0.f ? x : 0.f; }
__device__ __forceinline__ float lrelu_f(float x) { return x > 0.f ? x : 0.1f * x; }

__device__ __forceinline__ uint32_t smem_u32(const void* p) {
    uint32_t a;
    asm("{ .reg .u64 t; cvta.to.shared.u64 t, %1; cvt.u32.u64 %0, t; }" : "=r"(a) : "l"(p));
    return a;
}
__device__ __forceinline__ void ldsm4(uint32_t* r, uint32_t a) {
    asm volatile("ldmatrix.sync.aligned.m8n8.x4.shared.b16 {%0,%1,%2,%3}, [%4];"
                 : "=r"(r[0]), "=r"(r[1]), "=r"(r[2]), "=r"(r[3]) : "r"(a));
}
__device__ __forceinline__ void mma16816h(float* d, const uint32_t* a, const uint32_t* b) {
    asm volatile(
        "mma.sync.aligned.m16n8k16.row.col.f32.f16.f16.f32 "
        "{%0,%1,%2,%3}, {%4,%5,%6,%7}, {%8,%9}, {%0,%1,%2,%3};"
        : "+f"(d[0]), "+f"(d[1]), "+f"(d[2]), "+f"(d[3])
        : "r"(a[0]), "r"(a[1]), "r"(a[2]), "r"(a[3]), "r"(b[0]), "r"(b[1]));
}
__device__ __forceinline__ void cp16(uint32_t dst, const void* src) {
    asm volatile("cp.async.cg.shared.global [%0], [%1], 16;" :: "r"(dst), "l"(src));
}
#define CP_COMMIT() asm volatile("cp.async.commit_group;" ::: "memory")
#define CP_WAIT1() asm volatile("cp.async.wait_group 1;" ::: "memory")
#define CP_WAIT0() asm volatile("cp.async.wait_group 0;" ::: "memory")

__device__ __forceinline__ uint32_t packh2(float x, float y) {
    __half2 h = __floats2half2_rn(x, y);
    return *(uint32_t*)&h;
}

// ======================= K0: weight conversions (fp16 hi/lo) ===============
__global__ void __launch_bounds__(256) k0_wconv(
    const float* __restrict__ wlin, const float* __restrict__ wu2,
    const float* __restrict__ wsc) {
    int i = blockIdx.x * 256 + threadIdx.x;
    if (i < 512 * 64) {
        int n = i >> 9, k = i & 511;
        float v = __ldg(&wlin[k * 64 + n]);
        __half h = __float2half_rn(v);
        g_bh16[i] = h;
        g_bl16[i] = __float2half_rn(v - __half2float(h));
    }
    if (i < 128 * 128) {
        int n = i >> 7, k = i & 127;
        float v = (k < 64) ? __ldg(&wu2[k * 128 + n]) : __ldg(&wsc[(k - 64) * 128 + n]);
        __half h = __float2half_rn(v);
        g_b2h16[i] = h;
        g_b2l16[i] = __float2half_rn(v - __half2float(h));
    }
}

// ======================= K1: dense transform + gw1 =========================
__global__ void __launch_bounds__(256) k1_dense(
    const float* __restrict__ df,
    const float* __restrict__ w1, const float* __restrict__ b1,
    const float* __restrict__ wgu, const float* __restrict__ bgu,
    const float* __restrict__ wg1) {
    __shared__ __align__(16) float s_w1[64 * 32];
    __shared__ __align__(16) float s_wgu[32 * 32];
    __shared__ __align__(16) float s_wg1k[32 * 8];
    __shared__ union {
        float f[128][68];
        float fx[128][36];
    } u;
    int t = threadIdx.x;
    int p0 = blockIdx.x * 128;
    for (int i = t; i < 2048; i += 256) s_w1[i] = w1[i];
    for (int i = t; i < 1024; i += 256) s_wgu[i] = wgu[i];
    if (t < 256) s_wg1k[t] = wg1[t];
#pragma unroll
    for (int q = 0; q < 8; q++) {
        int id = t + q * 256;
        int pp = id >> 4, kk = (id & 15) * 4;
        int gm = p0 + pp; if (gm >= NPTS) gm = NPTS - 1;
        *(float4*)&u.f[pp][kk] = *(const float4*)(df + (size_t)gm * 64 + kk);
    }
    __syncthreads();

    int pg = t >> 3, cg = t & 7;
    int c4 = cg * 4;
    float4 bb = *(const float4*)(b1 + c4);
    float acc[4][4];
#pragma unroll
    for (int i = 0; i < 4; i++) { acc[i][0] = bb.x; acc[i][1] = bb.y; acc[i][2] = bb.z; acc[i][3] = bb.w; }
#pragma unroll
    for (int kb = 0; kb < 64; kb += 4) {
        float4 a[4];
#pragma unroll
        for (int i = 0; i < 4; i++) a[i] = *(const float4*)&u.f[pg * 4 + i][kb];
#pragma unroll
        for (int q = 0; q < 4; q++) {
            float4 w = *(const float4*)&s_w1[(kb + q) * 32 + c4];
#pragma unroll
            for (int i = 0; i < 4; i++) {
                float av = q == 0 ? a[i].x : q == 1 ? a[i].y : q == 2 ? a[i].z : a[i].w;
                acc[i][0] = fmaf(av, w.x, acc[i][0]); acc[i][1] = fmaf(av, w.y, acc[i][1]);
                acc[i][2] = fmaf(av, w.z, acc[i][2]); acc[i][3] = fmaf(av, w.w, acc[i][3]);
            }
        }
    }
    float4 fxv[4];
#pragma unroll
    for (int i = 0; i < 4; i++)
        fxv[i] = make_float4(lrelu_f(acc[i][0]), lrelu_f(acc[i][1]), lrelu_f(acc[i][2]), lrelu_f(acc[i][3]));
    __syncthreads();
#pragma unroll
    for (int i = 0; i < 4; i++) {
        int gm = p0 + pg * 4 + i;
        *(float4*)&u.fx[pg * 4 + i][c4] = fxv[i];
        if (gm < NPTS) *(float4*)(g_fx + (size_t)gm * 32 + c4) = fxv[i];
    }
    __syncthreads();

    float4 bg = *(const float4*)(bgu + c4);
    float gac[4][4];
#pragma unroll
    for (int i = 0; i < 4; i++) { gac[i][0] = bg.x; gac[i][1] = bg.y; gac[i][2] = bg.z; gac[i][3] = bg.w; }
#pragma unroll
    for (int kb = 0; kb < 32; kb += 4) {
        float4 a[4];
#pragma unroll
        for (int i = 0; i < 4; i++) a[i] = *(const float4*)&u.fx[pg * 4 + i][kb];
#pragma unroll
        for (int q = 0; q < 4; q++) {
            float4 w = *(const float4*)&s_wgu[(kb + q) * 32 + c4];
#pragma unroll
            for (int i = 0; i < 4; i++) {
                float av = q == 0 ? a[i].x : q == 1 ? a[i].y : q == 2 ? a[i].z : a[i].w;
                gac[i][0] = fmaf(av, w.x, gac[i][0]); gac[i][1] = fmaf(av, w.y, gac[i][1]);
                gac[i][2] = fmaf(av, w.z, gac[i][2]); gac[i][3] = fmaf(av, w.w, gac[i][3]);
            }
        }
    }
    __syncthreads();
#pragma unroll
    for (int i = 0; i < 4; i++) {
        int gm = p0 + pg * 4 + i;
        *(float4*)&u.fx[pg * 4 + i][c4] =
            make_float4(gac[i][0], gac[i][1], gac[i][2], gac[i][3]);
        if (gm < NPTS)
            *(float4*)(g_gx + (size_t)gm * 32 + c4) =
                make_float4(gac[i][0], gac[i][1], gac[i][2], gac[i][3]);
    }
    __syncthreads();

    {
        int p2 = t >> 1, h4 = (t & 1) * 4;
        float o4[4] = {0.f, 0.f, 0.f, 0.f};
#pragma unroll
        for (int c = 0; c < 32; c++) {
            float g = u.fx[p2][c];
            float4 w = *(const float4*)&s_wg1k[c * 8 + h4];
            o4[0] = fmaf(g, w.x, o4[0]); o4[1] = fmaf(g, w.y, o4[1]);
            o4[2] = fmaf(g, w.z, o4[2]); o4[3] = fmaf(g, w.w, o4[3]);
        }
        int gm = p0 + p2;
        if (gm < NPTS)
            *(float4*)(g_gw1 + (size_t)gm * 8 + h4) = make_float4(o4[0], o4[1], o4[2], o4[3]);
    }
}

// ======================= K6: dense PE/WeightNet + pe channel-max ===========
__global__ void __launch_bounds__(256) k6_pewn(
    const float* __restrict__ vi_f,
    const float* __restrict__ wpe, const float* __restrict__ bpe,
    const float* __restrict__ wg1,
    const float* __restrict__ wn1, const float* __restrict__ bn1,
    const float* __restrict__ wn2, const float* __restrict__ bn2,
    const float* __restrict__ wn3, const float* __restrict__ bn3) {
    __shared__ __align__(16) float s_wpet[32 * 12];
    __shared__ __align__(16) float s_w1h[32 * 8];
    __shared__ __align__(16) float s_wn1t[8 * 12];
    __shared__ __align__(16) float s_wn2t[8 * 8];
    __shared__ __align__(16) float s_wn3t[16 * 8];
    __shared__ float s_bpe[32], s_bn1[8], s_bn2[8], s_bn3[16];
    __shared__ __align__(16) float s_tmp[256][36];
    int t = threadIdx.x;
    for (int i = t; i < 384; i += 256) { int c = i / 12, ii = i % 12; s_wpet[i] = wpe[ii * 32 + c]; }
    if (t < 256) s_w1h[t] = wg1[256 + t];
    if (t < 96) { int o = t / 12, ii = t % 12; s_wn1t[t] = wn1[ii * 8 + o]; }
    if (t < 64) s_wn2t[t] = wn2[(t & 7) * 8 + (t >> 3)];
    if (t < 128) { int o = t >> 3, ii = t & 7; s_wn3t[t] = wn3[ii * 16 + o]; }
    if (t < 32) s_bpe[t] = bpe[t];
    if (t < 8) { s_bn1[t] = bn1[t]; s_bn2[t] = bn2[t]; }
    if (t < 16) s_bn3[t] = bn3[t];
    __syncthreads();

    size_t r0 = (size_t)blockIdx.x * 512 + t * 2;
    float va[12], vb[12];
    {
        const float4* p = (const float4*)(vi_f + r0 * 12);
        float4 x0 = p[0], x1 = p[1], x2 = p[2], x3 = p[3], x4 = p[4], x5 = p[5];
        va[0] = x0.x; va[1] = x0.y; va[2] = x0.z; va[3] = x0.w;
        va[4] = x1.x; va[5] = x1.y; va[6] = x1.z; va[7] = x1.w;
        va[8] = x2.x; va[9] = x2.y; va[10] = x2.z; va[11] = x2.w;
        vb[0] = x3.x; vb[1] = x3.y; vb[2] = x3.z; vb[3] = x3.w;
        vb[4] = x4.x; vb[5] = x4.y; vb[6] = x4.z; vb[7] = x4.w;
        vb[8] = x5.x; vb[9] = x5.y; vb[10] = x5.z; vb[11] = x5.w;
    }

    float pwa[8], pwb[8];
#pragma unroll
    for (int h = 0; h < 8; h++) { pwa[h] = 0.f; pwb[h] = 0.f; }
#pragma unroll
    for (int c = 0; c < 32; c++) {
        const float4* wr = (const float4*)&s_wpet[c * 12];
        float4 w0 = wr[0], w1v = wr[1], w2 = wr[2];
        float bias = s_bpe[c];
        float a = bias, b = bias;
        a = fmaf(va[0], w0.x, a);  b = fmaf(vb[0], w0.x, b);
        a = fmaf(va[1], w0.y, a);  b = fmaf(vb[1], w0.y, b);
        a = fmaf(va[2], w0.z, a);  b = fmaf(vb[2], w0.z, b);
        a = fmaf(va[3], w0.w, a);  b = fmaf(vb[3], w0.w, b);
        a = fmaf(va[4], w1v.x, a); b = fmaf(vb[4], w1v.x, b);
        a = fmaf(va[5], w1v.y, a); b = fmaf(vb[5], w1v.y, b);
        a = fmaf(va[6], w1v.z, a); b = fmaf(vb[6], w1v.z, b);
        a = fmaf(va[7], w1v.w, a); b = fmaf(vb[7], w1v.w, b);
        a = fmaf(va[8], w2.x, a);  b = fmaf(vb[8], w2.x, b);
        a = fmaf(va[9], w2.y, a);  b = fmaf(vb[9], w2.y, b);
        a = fmaf(va[10], w2.z, a); b = fmaf(vb[10], w2.z, b);
        a = fmaf(va[11], w2.w, a); b = fmaf(vb[11], w2.w, b);
        float ra = relu_f(a), rb = relu_f(b);
        s_tmp[t][c] = fmaxf(ra, rb);
        const float4* wh = (const float4*)&s_w1h[c * 8];
        float4 ha = wh[0], hb = wh[1];
        pwa[0] = fmaf(ra, ha.x, pwa[0]); pwa[1] = fmaf(ra, ha.y, pwa[1]);
        pwa[2] = fmaf(ra, ha.z, pwa[2]); pwa[3] = fmaf(ra, ha.w, pwa[3]);
        pwa[4] = fmaf(ra, hb.x, pwa[4]); pwa[5] = fmaf(ra, hb.y, pwa[5]);
        pwa[6] = fmaf(ra, hb.z, pwa[6]); pwa[7] = fmaf(ra, hb.w, pwa[7]);
        pwb[0] = fmaf(rb, ha.x, pwb[0]); pwb[1] = fmaf(rb, ha.y, pwb[1]);
        pwb[2] = fmaf(rb, ha.z, pwb[2]); pwb[3] = fmaf(rb, ha.w, pwb[3]);
        pwb[4] = fmaf(rb, hb.x, pwb[4]); pwb[5] = fmaf(rb, hb.y, pwb[5]);
        pwb[6] = fmaf(rb, hb.z, pwb[6]); pwb[7] = fmaf(rb, hb.w, pwb[7]);
    }
    // pw -> fp16 (8 halves = 16B per row)
    {
        uint4 pa16, pb16;
        pa16.x = packh2(pwa[0], pwa[1]); pa16.y = packh2(pwa[2], pwa[3]);
        pa16.z = packh2(pwa[4], pwa[5]); pa16.w = packh2(pwa[6], pwa[7]);
        pb16.x = packh2(pwb[0], pwb[1]); pb16.y = packh2(pwb[2], pwb[3]);
        pb16.z = packh2(pwb[4], pwb[5]); pb16.w = packh2(pwb[6], pwb[7]);
        *(uint4*)(g_pw116 + r0 * 8) = pa16;
        *(uint4*)(g_pw116 + (r0 + 1) * 8) = pb16;
    }

    float h1a[8], h1b[8];
#pragma unroll
    for (int o = 0; o < 8; o++) {
        const float4* wr = (const float4*)&s_wn1t[o * 12];
        float4 w0 = wr[0], w1v = wr[1], w2 = wr[2];
        float bias = s_bn1[o];
        float a = bias, b = bias;
        a = fmaf(va[0], w0.x, a);  b = fmaf(vb[0], w0.x, b);
        a = fmaf(va[1], w0.y, a);  b = fmaf(vb[1], w0.y, b);
        a = fmaf(va[2], w0.z, a);  b = fmaf(vb[2], w0.z, b);
        a = fmaf(va[3], w0.w, a);  b = fmaf(vb[3], w0.w, b);
        a = fmaf(va[4], w1v.x, a); b = fmaf(vb[4], w1v.x, b);
        a = fmaf(va[5], w1v.y, a); b = fmaf(vb[5], w1v.y, b);
        a = fmaf(va[6], w1v.z, a); b = fmaf(vb[6], w1v.z, b);
        a = fmaf(va[7], w1v.w, a); b = fmaf(vb[7], w1v.w, b);
        a = fmaf(va[8], w2.x, a);  b = fmaf(vb[8], w2.x, b);
        a = fmaf(va[9], w2.y, a);  b = fmaf(vb[9], w2.y, b);
        a = fmaf(va[10], w2.z, a); b = fmaf(vb[10], w2.z, b);
        a = fmaf(va[11], w2.w, a); b = fmaf(vb[11], w2.w, b);
        h1a[o] = relu_f(a); h1b[o] = relu_f(b);
    }
    float h2a[8], h2b[8];
#pragma unroll
    for (int o = 0; o < 8; o++) {
        const float4* wr = (const float4*)&s_wn2t[o * 8];
        float4 wx = wr[0], wy = wr[1];
        float bias = s_bn2[o];
        float a = bias, b = bias;
        a = fmaf(h1a[0], wx.x, a); b = fmaf(h1b[0], wx.x, b);
        a = fmaf(h1a[1], wx.y, a); b = fmaf(h1b[1], wx.y, b);
        a = fmaf(h1a[2], wx.z, a); b = fmaf(h1b[2], wx.z, b);
        a = fmaf(h1a[3], wx.w, a); b = fmaf(h1b[3], wx.w, b);
        a = fmaf(h1a[4], wy.x, a); b = fmaf(h1b[4], wy.x, b);
        a = fmaf(h1a[5], wy.y, a); b = fmaf(h1b[5], wy.y, b);
        a = fmaf(h1a[6], wy.z, a); b = fmaf(h1b[6], wy.z, b);
        a = fmaf(h1a[7], wy.w, a); b = fmaf(h1b[7], wy.w, b);
        h2a[o] = relu_f(a); h2b[o] = relu_f(b);
    }
    float pa[4], pb[4];
#pragma unroll
    for (int o = 0; o < 16; o++) {
        const float4* wr = (const float4*)&s_wn3t[o * 8];
        float4 wx = wr[0], wy = wr[1];
        float bias = s_bn3[o];
        float a = bias, b = bias;
        a = fmaf(h2a[0], wx.x, a); b = fmaf(h2b[0], wx.x, b);
        a = fmaf(h2a[1], wx.y, a); b = fmaf(h2b[1], wx.y, b);
        a = fmaf(h2a[2], wx.z, a); b = fmaf(h2b[2], wx.z, b);
        a = fmaf(h2a[3], wx.w, a); b = fmaf(h2b[3], wx.w, b);
        a = fmaf(h2a[4], wy.x, a); b = fmaf(h2b[4], wy.x, b);
        a = fmaf(h2a[5], wy.y, a); b = fmaf(h2b[5], wy.y, b);
        a = fmaf(h2a[6], wy.z, a); b = fmaf(h2b[6], wy.z, b);
        a = fmaf(h2a[7], wy.w, a); b = fmaf(h2b[7], wy.w, b);
        pa[o & 3] = relu_f(a); pb[o & 3] = relu_f(b);
        if ((o & 3) == 3) {
            uint2 qa, qb;
            qa.x = packh2(pa[0], pa[1]); qa.y = packh2(pa[2], pa[3]);
            qb.x = packh2(pb[0], pb[1]); qb.y = packh2(pb[2], pb[3]);
            *(uint2*)(g_w16 + r0 * 16 + (o - 3)) = qa;
            *(uint2*)(g_w16 + (r0 + 1) * 16 + (o - 3)) = qb;
        }
    }

    __syncthreads();
    int pt = t >> 3, ch0 = (t & 7) * 4;
    int base = pt * 8;
    float4 vm = *(const float4*)&s_tmp[base][ch0];
#pragma unroll
    for (int k = 1; k < 8; k++) {
        float4 v = *(const float4*)&s_tmp[base + k][ch0];
        vm.x = fmaxf(vm.x, v.x); vm.y = fmaxf(vm.y, v.y);
        vm.z = fmaxf(vm.z, v.z); vm.w = fmaxf(vm.w, v.w);
    }
    *(float4*)(g_pemax + (size_t)(blockIdx.x * 32 + pt) * 32 + ch0) = vm;
}

// ======================= K5: shortcut maxpool (fp16 out) ===================
__global__ void __launch_bounds__(256) k5_maxpool(
    const float* __restrict__ df, const int* __restrict__ nei) {
    const unsigned FULL = 0xffffffffu;
    int t = threadIdx.x;
    int wid = t >> 5, lane = t & 31;
    int m = blockIdx.x * 8 + wid;
    int j = lane >> 1;
    int idx = __ldg(&nei[m * 16 + j]);
    float m0v = -3.0e38f, m1v = -3.0e38f;
#pragma unroll
    for (int jj = 0; jj < 16; jj++) {
        int ix = __shfl_sync(FULL, idx, jj * 2);
        m0v = fmaxf(m0v, __ldg(&df[(size_t)ix * 64 + lane]));
        m1v = fmaxf(m1v, __ldg(&df[(size_t)ix * 64 + 32 + lane]));
    }
    g_sf16[(size_t)m * 64 + lane] = __float2half_rn(m0v);
    g_sf16[(size_t)m * 64 + 32 + lane] = __float2half_rn(m1v);
}

// ======================= K2: gather + attention + agg ======================
__global__ void __launch_bounds__(256, 2) k2_point(
    const int* __restrict__ nei,
    const float* __restrict__ wg1, const float* __restrict__ bg1,
    const float* __restrict__ wg2, const float* __restrict__ bg2) {
    __shared__ __align__(16) float s_wg1[64 * 8];
    __shared__ __align__(16) float s_wg2t[8 * 8];
    __shared__ float s_bg1[8], s_bg2[8];
    __shared__ __align__(16) float s_gf[8][16][36];
    __shared__ __align__(16) float s_nf[8][16][36];
    __shared__ __align__(16) float s_w[8][16][20];
    __shared__ __align__(16) __half s_w16[8][16][16];   // staging for fp16 w
    int t = threadIdx.x;
    for (int i = t; i < 512; i += 256) s_wg1[i] = wg1[i];
    if (t < 64) s_wg2t[t] = wg2[(t & 7) * 8 + (t >> 3)];
    if (t < 8) { s_bg1[t] = bg1[t]; s_bg2[t] = bg2[t]; }
    __syncthreads();

    const unsigned FULL = 0xffffffffu;
    int wid = t >> 5, lane = t & 31;
    int j = lane >> 1, half = lane & 1;
    int m = blockIdx.x * 8 + wid;
    int idx = __ldg(&nei[m * 16 + j]);
    size_t row = (size_t)m * 16 + j;

    {
        const char* gsrc = (const char*)(g_gx + (size_t)idx * 32 + half * 16);
        uint32_t gdst = smem_u32(&s_gf[wid][j][half * 16]);
        cp16(gdst, gsrc); cp16(gdst + 16, gsrc + 16);
        cp16(gdst + 32, gsrc + 32); cp16(gdst + 48, gsrc + 48);
        const char* fsrc = (const char*)(g_fx + (size_t)idx * 32 + half * 16);
        uint32_t fdst = smem_u32(&s_nf[wid][j][half * 16]);
        cp16(fdst, fsrc); cp16(fdst + 16, fsrc + 16);
        cp16(fdst + 32, fsrc + 32); cp16(fdst + 48, fsrc + 48);
        cp16(smem_u32(&s_w16[wid][j][half * 8]), (const char*)(g_w16 + row * 16 + half * 8));
        CP_COMMIT();
    }
    // part: half0 = gathered-guidance@W1lo (fp32); half1 = pe@W1hi (fp16)
    float part[8];
    if (half) {
        uint4 p16 = *(const uint4*)(g_pw116 + row * 8);
        __half2 h0 = *(__half2*)&p16.x, h1 = *(__half2*)&p16.y;
        __half2 h2 = *(__half2*)&p16.z, h3 = *(__half2*)&p16.w;
        float2 f0 = __half22float2(h0), f1 = __half22float2(h1);
        float2 f2 = __half22float2(h2), f3 = __half22float2(h3);
        part[0] = f0.x; part[1] = f0.y; part[2] = f1.x; part[3] = f1.y;
        part[4] = f2.x; part[5] = f2.y; part[6] = f3.x; part[7] = f3.y;
    } else {
        float4 a0 = __ldg((const float4*)(g_gw1 + (size_t)idx * 8));
        float4 a1 = __ldg((const float4*)(g_gw1 + (size_t)idx * 8 + 4));
        part[0] = a0.x; part[1] = a0.y; part[2] = a0.z; part[3] = a0.w;
        part[4] = a1.x; part[5] = a1.y; part[6] = a1.z; part[7] = a1.w;
    }
    float mx1 = __ldg(&g_pemax[(size_t)m * 32 + lane]);

    CP_WAIT0();
    // convert own w fp16 -> fp32 into s_w
    {
        uint4 w16 = *(const uint4*)&s_w16[wid][j][half * 8];
        __half2 h0 = *(__half2*)&w16.x, h1 = *(__half2*)&w16.y;
        __half2 h2 = *(__half2*)&w16.z, h3 = *(__half2*)&w16.w;
        float2 f0 = __half22float2(h0), f1 = __half22float2(h1);
        float2 f2 = __half22float2(h2), f3 = __half22float2(h3);
        *(float4*)&s_w[wid][j][half * 8] = make_float4(f0.x, f0.y, f1.x, f1.y);
        *(float4*)&s_w[wid][j][half * 8 + 4] = make_float4(f2.x, f2.y, f3.x, f3.y);
    }
    __syncwarp();

    float mx0 = -3.0e38f;
    int cl = lane;
#pragma unroll
    for (int jj = 0; jj < 16; jj++)
        mx0 = fmaxf(mx0, s_gf[wid][jj][cl]);
    float mw[8];
    {
        const float4* wr0 = (const float4*)&s_wg1[cl * 8];
        const float4* wr1 = (const float4*)&s_wg1[(cl + 32) * 8];
        float4 a0 = wr0[0], a1 = wr0[1], b0 = wr1[0], b1v = wr1[1];
        mw[0] = fmaf(mx0, a0.x, mx1 * b0.x); mw[1] = fmaf(mx0, a0.y, mx1 * b0.y);
        mw[2] = fmaf(mx0, a0.z, mx1 * b0.z); mw[3] = fmaf(mx0, a0.w, mx1 * b0.w);
        mw[4] = fmaf(mx0, a1.x, mx1 * b1v.x); mw[5] = fmaf(mx0, a1.y, mx1 * b1v.y);
        mw[6] = fmaf(mx0, a1.z, mx1 * b1v.z); mw[7] = fmaf(mx0, a1.w, mx1 * b1v.w);
    }
#pragma unroll
    for (int s = 16; s >= 1; s >>= 1) {
#pragma unroll
        for (int h = 0; h < 8; h++) mw[h] += __shfl_xor_sync(FULL, mw[h], s);
    }
#pragma unroll
    for (int h = 0; h < 8; h++) part[h] += __shfl_xor_sync(FULL, part[h], 1);

    float s1v[8];
#pragma unroll
    for (int h = 0; h < 8; h++) s1v[h] = relu_f(part[h] - mw[h] + s_bg1[h]);
    float sc4[4];
#pragma unroll
    for (int hq = 0; hq < 4; hq++) {
        int h2 = half * 4 + hq;
        float a = s_bg2[h2];
        const float4* wr = (const float4*)&s_wg2t[h2 * 8];
        float4 wa = wr[0], wb = wr[1];
        a = fmaf(s1v[0], wa.x, a); a = fmaf(s1v[1], wa.y, a);
        a = fmaf(s1v[2], wa.z, a); a = fmaf(s1v[3], wa.w, a);
        a = fmaf(s1v[4], wb.x, a); a = fmaf(s1v[5], wb.y, a);
        a = fmaf(s1v[6], wb.z, a); a = fmaf(s1v[7], wb.w, a);
        sc4[hq] = 1.f / (1.f + __expf(-a));
    }

#pragma unroll
    for (int q = 0; q < 4; q++) {
        int c0 = half * 16 + 4 * q;
        float4 v = *(const float4*)&s_nf[wid][j][c0];
        float s = sc4[q];
        *(float4*)&s_nf[wid][j][c0] = make_float4(v.x * s, v.y * s, v.z * s, v.w * s);
    }
    __syncwarp();

    float acc[16];
#pragma unroll
    for (int w = 0; w < 16; w++) acc[w] = 0.f;
    int c = lane;
#pragma unroll
    for (int jj = 0; jj < 16; jj++) {
        float a = s_nf[wid][jj][c];
        const float4* wp = (const float4*)&s_w[wid][jj][0];
        float4 w0 = wp[0], w1v = wp[1], w2 = wp[2], w3 = wp[3];
        acc[0] = fmaf(a, w0.x, acc[0]);  acc[1] = fmaf(a, w0.y, acc[1]);
        acc[2] = fmaf(a, w0.z, acc[2]);  acc[3] = fmaf(a, w0.w, acc[3]);
        acc[4] = fmaf(a, w1v.x, acc[4]); acc[5] = fmaf(a, w1v.y, acc[5]);
        acc[6] = fmaf(a, w1v.z, acc[6]); acc[7] = fmaf(a, w1v.w, acc[7]);
        acc[8] = fmaf(a, w2.x, acc[8]);  acc[9] = fmaf(a, w2.y, acc[9]);
        acc[10] = fmaf(a, w2.z, acc[10]); acc[11] = fmaf(a, w2.w, acc[11]);
        acc[12] = fmaf(a, w3.x, acc[12]); acc[13] = fmaf(a, w3.y, acc[13]);
        acc[14] = fmaf(a, w3.z, acc[14]); acc[15] = fmaf(a, w3.w, acc[15]);
    }
    __align__(16) __half hb[16];
#pragma unroll
    for (int w = 0; w < 16; w++) hb[w] = __float2half_rn(acc[w]);
    size_t bo = (size_t)m * 512 + c * 16;
    ((uint4*)(g_agg + bo))[0] = ((uint4*)hb)[0];
    ((uint4*)(g_agg + bo))[1] = ((uint4*)hb)[1];
}

// ======================= K34: fused GEMM1 + GEMM2 (fp16 A) =================
#define K3_A    0u
#define K3_B_HI 36864u
#define K3_B_LO 55296u
#define K4_A2   36864u
#define K4_B_HI 55296u
#define K4_B_LO 73728u
#define K34_SMEM 92160

__device__ __forceinline__ void k3_load(uint32_t sb, int t, int m0, int kt, int st) {
    uint32_t aofs = (uint32_t)st * 18432u;
    uint32_t bofs = (uint32_t)st * 9216u;
#pragma unroll
    for (int q = 0; q < 4; q++) {
        int id = t + q * 256;
        int row = id >> 3, seg = id & 7;
        int gm = m0 + row; if (gm >= MPTS) gm = MPTS - 1;
        size_t go = (size_t)gm * 512 + kt * 64 + seg * 8;
        uint32_t so_ = (uint32_t)(row * 144 + seg * 16);
        cp16(sb + K3_A + aofs + so_, g_agg + go);
    }
#pragma unroll
    for (int q = 0; q < 2; q++) {
        int id = t + q * 256;
        int n = id >> 3, seg = id & 7;
        size_t go = (size_t)n * 512 + kt * 64 + seg * 8;
        uint32_t so_ = (uint32_t)(n * 144 + seg * 16);
        cp16(sb + K3_B_HI + bofs + so_, g_bh16 + go);
        cp16(sb + K3_B_LO + bofs + so_, g_bl16 + go);
    }
}

__global__ void __launch_bounds__(256, 2) k34_out(
    const float* __restrict__ blin,
    const float* __restrict__ bu2, const float* __restrict__ bsc,
    float* __restrict__ out) {
    extern __shared__ __align__(16) char dsm[];
    uint32_t sb = smem_u32(dsm);
    int t = threadIdx.x;
    int wid = t >> 5, lane = t & 31;
    int m0 = blockIdx.x * 128;
    int wm = wid * 16;
    int qq = lane >> 3, rr = lane & 7;

    // ---------------- Phase 1: GEMM1 ----------------
    {
        float acc[8][4];
#pragma unroll
        for (int nt = 0; nt < 8; nt++)
#pragma unroll
            for (int q = 0; q < 4; q++) acc[nt][q] = 0.f;

        k3_load(sb, t, m0, 0, 0);
        CP_COMMIT();

#pragma unroll 1
        for (int kt = 0; kt < 8; kt++) {
            int st = kt & 1;
            if (kt < 7) {
                k3_load(sb, t, m0, kt + 1, st ^ 1);
                CP_COMMIT();
                CP_WAIT1();
            } else {
                CP_WAIT0();
            }
            __syncthreads();

            uint32_t aofs = (uint32_t)st * 18432u;
            uint32_t bofs = (uint32_t)st * 9216u;
#pragma unroll
            for (int ks = 0; ks < 4; ks++) {
                int k0 = ks * 16;
                uint32_t ah[4];
                {
                    int row = wm + rr + (qq & 1) * 8;
                    int col = k0 + (qq >> 1) * 8;
                    ldsm4(ah, sb + K3_A + aofs + (uint32_t)(row * 144 + col * 2));
                }
#pragma unroll
                for (int p = 0; p < 4; p++) {
                    uint32_t bh4[4], bl4[4];
                    int noff = 16 * p + rr + (qq >> 1) * 8;
                    int col = k0 + (qq & 1) * 8;
                    uint32_t bd = sb + K3_B_HI + bofs + (uint32_t)(noff * 144 + col * 2);
                    ldsm4(bh4, bd);
                    ldsm4(bl4, bd + (K3_B_LO - K3_B_HI));
                    mma16816h(acc[2 * p], ah, bh4);
                    mma16816h(acc[2 * p + 1], ah, bh4 + 2);
                    mma16816h(acc[2 * p], ah, bl4);
                    mma16816h(acc[2 * p + 1], ah, bl4 + 2);
                }
            }
            __syncthreads();
        }

        {
            int rrow = lane >> 2, cp = (lane & 3) * 2;
            float* so = (float*)dsm;
#pragma unroll
            for (int nt = 0; nt < 8; nt++) {
                int c0 = nt * 8 + cp;
                float b0v = __ldg(&blin[c0]), b1v = __ldg(&blin[c0 + 1]);
                so[(wm + rrow) * 65 + c0]         = relu_f(acc[nt][0] + b0v);
                so[(wm + rrow) * 65 + c0 + 1]     = relu_f(acc[nt][1] + b1v);
                so[(wm + rrow + 8) * 65 + c0]     = relu_f(acc[nt][2] + b0v);
                so[(wm + rrow + 8) * 65 + c0 + 1] = relu_f(acc[nt][3] + b1v);
            }
        }
        __syncthreads();
    }

    // ---------------- Phase 2: GEMM2 + final epilogue ----------------
    float acc2[16][4];
#pragma unroll
    for (int nt = 0; nt < 16; nt++)
#pragma unroll
        for (int q = 0; q < 4; q++) acc2[nt][q] = 0.f;

#pragma unroll 1
    for (int kt = 0; kt < 2; kt++) {
        if (kt == 0) {
            const float* so = (const float*)dsm;
#pragma unroll
            for (int q = 0; q < 4; q++) {
                int id = t + q * 256;
                int row = id >> 3, seg = id & 7;
                const float* src = so + row * 65 + seg * 8;
                uint32_t p0 = packh2(src[0], src[1]);
                uint32_t p1 = packh2(src[2], src[3]);
                uint32_t p2 = packh2(src[4], src[5]);
                uint32_t p3 = packh2(src[6], src[7]);
                asm volatile("st.shared.v4.b32 [%0], {%1,%2,%3,%4};"
                             :: "r"(sb + K4_A2 + (uint32_t)(row * 144 + seg * 16)),
                                "r"(p0), "r"(p1), "r"(p2), "r"(p3) : "memory");
            }
        } else {
#pragma unroll
            for (int q = 0; q < 4; q++) {
                int id = t + q * 256;
                int row = id >> 3, seg = id & 7;
                int gm = m0 + row; if (gm >= MPTS) gm = MPTS - 1;
                *(uint4*)(dsm + K4_A2 + (uint32_t)(row * 144 + seg * 16)) =
                    *(const uint4*)(g_sf16 + (size_t)gm * 64 + seg * 8);
            }
        }
#pragma unroll
        for (int q = 0; q < 4; q++) {
            int id = t + q * 256;
            int n = id >> 3, seg = id & 7;
            size_t go = (size_t)n * 128 + kt * 64 + seg * 8;
            uint32_t so_ = (uint32_t)(n * 144 + seg * 16);
            *(uint4*)(dsm + K4_B_HI + so_) = *(const uint4*)(g_b2h16 + go);
            *(uint4*)(dsm + K4_B_LO + so_) = *(const uint4*)(g_b2l16 + go);
        }
        __syncthreads();

#pragma unroll
        for (int ks = 0; ks < 4; ks++) {
            int k0 = ks * 16;
            uint32_t ah[4];
            {
                int row = wm + rr + (qq & 1) * 8;
                int col = k0 + (qq >> 1) * 8;
                ldsm4(ah, sb + K4_A2 + (uint32_t)(row * 144 + col * 2));
            }
#pragma unroll
            for (int p = 0; p < 8; p++) {
                uint32_t bh4[4], bl4[4];
                int noff = 16 * p + rr + (qq >> 1) * 8;
                int col = k0 + (qq & 1) * 8;
                uint32_t bd = sb + K4_B_HI + (uint32_t)(noff * 144 + col * 2);
                ldsm4(bh4, bd);
                ldsm4(bl4, bd + (K4_B_LO - K4_B_HI));
                mma16816h(acc2[2 * p], ah, bh4);
                mma16816h(acc2[2 * p + 1], ah, bh4 + 2);
                mma16816h(acc2[2 * p], ah, bl4);
                mma16816h(acc2[2 * p + 1], ah, bl4 + 2);
            }
        }
        __syncthreads();
    }

    int r0 = lane >> 2, cp = (lane & 3) * 2;
    int mA = m0 + wm + r0, mB = mA + 8;
#pragma unroll
    for (int nt = 0; nt < 16; nt++) {
        int c0 = nt * 8 + cp;
        float b0v = __ldg(&bu2[c0]) + __ldg(&bsc[c0]);
        float b1v = __ldg(&bu2[c0 + 1]) + __ldg(&bsc[c0 + 1]);
        if (mA < MPTS)
            *(float2*)(out + (size_t)mA * 128 + c0) =
                make_float2(lrelu_f(acc2[nt][0] + b0v), lrelu_f(acc2[nt][1] + b1v));
        if (mB < MPTS)
            *(float2*)(out + (size_t)mB * 128 + c0) =
                make_float2(lrelu_f(acc2[nt][2] + b0v), lrelu_f(acc2[nt][3] + b1v));
    }
}

// ======================= launch ============================================
extern "C" void kernel_launch(void* const* d_in, const int* in_sizes, int n_in,
                              void* d_out, int out_size) {
    const float* df  = (const float*)d_in[1];
    const float* vi  = (const float*)d_in[5];
    const int*   nei = (const int*)d_in[6];
    const float* w1  = (const float*)d_in[7];
    const float* b1  = (const float*)d_in[8];
    const float* wgu = (const float*)d_in[9];
    const float* bgu = (const float*)d_in[10];
    const float* wpe = (const float*)d_in[11];
    const float* bpe = (const float*)d_in[12];
    const float* wg1 = (const float*)d_in[13];
    const float* bg1 = (const float*)d_in[14];
    const float* wg2 = (const float*)d_in[15];
    const float* bg2 = (const float*)d_in[16];
    const float* wn1 = (const float*)d_in[17];
    const float* bn1 = (const float*)d_in[18];
    const float* wn2 = (const float*)d_in[19];
    const float* bn2 = (const float*)d_in[20];
    const float* wn3 = (const float*)d_in[21];
    const float* bn3 = (const float*)d_in[22];
    const float* wlin = (const float*)d_in[23];
    const float* blin = (const float*)d_in[24];
    const float* wu2 = (const float*)d_in[25];
    const float* bu2 = (const float*)d_in[26];
    const float* wsc = (const float*)d_in[27];
    const float* bsc = (const float*)d_in[28];
    float* out = (float*)d_out;

    cudaFuncSetAttribute(k34_out, cudaFuncAttributeMaxDynamicSharedMemorySize, K34_SMEM);

    // k2 kept at launch index 3 (the one ncu captures).
    k0_wconv<<<128, 256>>>(wlin, wu2, wsc);
    k1_dense<<<(NPTS + 127) / 128, 256>>>(df, w1, b1, wgu, bgu, wg1);
    k6_pewn<<<(MPTS * 16) / 512, 256>>>(vi, wpe, bpe, wg1,
                                        wn1, bn1, wn2, bn2, wn3, bn3);
    k2_point<<<MPTS / 8, 256>>>(nei, wg1, bg1, wg2, bg2);
    k5_maxpool<<<MPTS / 8, 256>>>(df, nei);
    k34_out<<<(MPTS + 127) / 128, 256, K34_SMEM>>>(blin, bu2, bsc, out);
}